// round 6
// baseline (speedup 1.0000x reference)
#include <cuda_runtime.h>
#include <cuda_bf16.h>
#include <math.h>

#define SEQ 2048
#define DIM 2880
#define NH 64
#define NKV 8
#define HD 64
#define QDIM (NH*HD)     // 4096
#define KVDIM (NKV*HD)   // 512
#define QKVN 5120        // 4096 + 512 + 512
#define KOFF 4096
#define VOFF 4608
#define WINDOW 128

typedef __nv_bfloat16 bf16;

// fp32 scratch
__device__ float g_qkv[SEQ * QKVN];    // 40 MB: q | k | v per row
__device__ float g_attn[SEQ * QDIM];   // 32 MB
__device__ float g_bqkv[QKVN];

// bf16 hi/lo split scratch
__device__ bf16 g_xh[SEQ * DIM],      g_xl[SEQ * DIM];
__device__ bf16 g_wch[QKVN * DIM],    g_wcl[QKVN * DIM];   // concat wq|wk|wv
__device__ bf16 g_woh[DIM * QDIM],    g_wol[DIM * QDIM];
__device__ bf16 g_ah[SEQ * QDIM],     g_al[SEQ * QDIM];

// ---------------------------------------------------------------------------
__global__ void split_bf16(const float* __restrict__ src,
                           bf16* __restrict__ hi, bf16* __restrict__ lo, int n)
{
    int i = (blockIdx.x * blockDim.x + threadIdx.x) * 4;
    if (i >= n) return;
    float4 v = *(const float4*)(src + i);
    bf16 h0 = __float2bfloat16_rn(v.x);
    bf16 h1 = __float2bfloat16_rn(v.y);
    bf16 h2 = __float2bfloat16_rn(v.z);
    bf16 h3 = __float2bfloat16_rn(v.w);
    bf16 l0 = __float2bfloat16_rn(v.x - __bfloat162float(h0));
    bf16 l1 = __float2bfloat16_rn(v.y - __bfloat162float(h1));
    bf16 l2 = __float2bfloat16_rn(v.z - __bfloat162float(h2));
    bf16 l3 = __float2bfloat16_rn(v.w - __bfloat162float(h3));
    __nv_bfloat162* hp = (__nv_bfloat162*)(hi + i);
    __nv_bfloat162* lp = (__nv_bfloat162*)(lo + i);
    hp[0] = __nv_bfloat162(h0, h1); hp[1] = __nv_bfloat162(h2, h3);
    lp[0] = __nv_bfloat162(l0, l1); lp[1] = __nv_bfloat162(l2, l3);
}

__global__ void concat_bias(const float* __restrict__ qb,
                            const float* __restrict__ kb,
                            const float* __restrict__ vb,
                            float* __restrict__ o)
{
    int i = blockIdx.x * blockDim.x + threadIdx.x;
    if (i < KOFF)       o[i] = qb[i];
    else if (i < VOFF)  o[i] = kb[i - KOFF];
    else if (i < QKVN)  o[i] = vb[i - VOFF];
}

// ---------------------------------------------------------------------------
// bf16x3 mma.sync GEMM (NT): C = Ah*Bh^T + Ah*Bl^T + Al*Bh^T + bias
// Block 128x256, BK=32, 4-stage cp.async ring (wait_group 2), XOR-swizzled
// 64B rows, 256 thr = 8 warps (2m x 4n), warp tile 64x64.
// Requires M%128==0, K%32==0; N guarded (B rows zfill, C col-masked).
// ---------------------------------------------------------------------------
#define TILEA 8192u     // 128 rows x 64B
#define TILEBB 16384u   // 256 rows x 64B
#define STGB (2u*TILEA + 2u*TILEBB)   // 48 KB
#define NSTG 4
#define GSMEM_BYTES (NSTG*STGB)       // 192 KB

__device__ __forceinline__ void cpa16(unsigned dst, const void* src) {
    asm volatile("cp.async.cg.shared.global [%0], [%1], 16;" :: "r"(dst), "l"(src));
}
__device__ __forceinline__ void cpa16p(unsigned dst, const void* src, int sz) {
    asm volatile("cp.async.cg.shared.global [%0], [%1], 16, %2;"
                 :: "r"(dst), "l"(src), "r"(sz));
}

__global__ __launch_bounds__(256) void gemm_bf16x3(
    const bf16* __restrict__ Ah, const bf16* __restrict__ Al,
    const bf16* __restrict__ Bh, const bf16* __restrict__ Bl,
    const float* __restrict__ bias, float* __restrict__ C,
    int M, int N, int K)
{
    extern __shared__ char dsm[];
    unsigned sb;
    { unsigned long long t = __cvta_generic_to_shared(dsm); sb = (unsigned)t; }

    const int tid  = threadIdx.x;
    const int wid  = tid >> 5;
    const int lane = tid & 31;
    const int bm   = blockIdx.y * 128;
    const int bn   = blockIdx.x * 256;
    const int wm   = (wid >> 2) * 64;     // 0 or 64
    const int wn   = (wid & 3) * 64;      // 0,64,128,192
    const int g    = lane >> 2;
    const int tg   = lane & 3;

    const int KT = K / 32;

#define SWOFF(r, c) ((unsigned)((r) * 64 + ((((c) ^ (((r) >> 1) & 3))) << 4)))

#define ISSUE_STAGE(sidx, k0)                                                  \
    do {                                                                       \
        const unsigned tb = sb + (unsigned)(sidx) * STGB;                      \
        _Pragma("unroll")                                                      \
        for (int it = 0; it < 2; it++) {                                       \
            const int idx = tid + it * 256;                                    \
            const int r = idx >> 2, c = idx & 3;                               \
            const unsigned so = SWOFF(r, c);                                   \
            const size_t ao = (size_t)(bm + r) * K + (k0) + c * 8;             \
            cpa16(tb + so,         Ah + ao);                                   \
            cpa16(tb + TILEA + so, Al + ao);                                   \
        }                                                                      \
        _Pragma("unroll")                                                      \
        for (int it = 0; it < 4; it++) {                                       \
            const int idx = tid + it * 256;                                    \
            const int r = idx >> 2, c = idx & 3;                               \
            const unsigned so = SWOFF(r, c);                                   \
            const int brw = bn + r;                                            \
            const int pz  = (brw < N) ? 16 : 0;                                \
            const size_t bo = (size_t)((brw < N) ? brw : 0) * K + (k0) + c * 8;\
            cpa16p(tb + 2 * TILEA + so,          Bh + bo, pz);                 \
            cpa16p(tb + 2 * TILEA + TILEBB + so, Bl + bo, pz);                 \
        }                                                                      \
        asm volatile("cp.async.commit_group;");                                \
    } while (0)

    float acc[4][8][4];
#pragma unroll
    for (int mi = 0; mi < 4; mi++)
#pragma unroll
        for (int ni = 0; ni < 8; ni++)
#pragma unroll
            for (int r = 0; r < 4; r++) acc[mi][ni][r] = 0.f;

    ISSUE_STAGE(0, 0);
    ISSUE_STAGE(1, 32);
    ISSUE_STAGE(2, 64);

    const int a_row = ((lane >> 3) & 1) * 8 + (lane & 7);
    const int a_ch  = (lane >> 4) & 1;
    const int b_row = ((lane >> 4) & 1) * 8 + (lane & 7);
    const int b_ch  = (lane >> 3) & 1;

    for (int kt = 0; kt < KT; kt++) {
        asm volatile("cp.async.wait_group %0;" :: "n"(2));
        __syncthreads();

        if (kt + 3 < KT) ISSUE_STAGE((kt + 3) % NSTG, (kt + 3) * 32);
        else             asm volatile("cp.async.commit_group;");

        const unsigned stb = sb + (unsigned)(kt % NSTG) * STGB;

#pragma unroll
        for (int ks = 0; ks < 2; ks++) {
            const int ca = ks * 2 + a_ch;
            const int cb = ks * 2 + b_ch;
            unsigned fAh[4][4], fAl[4][4], fBh[8][2], fBl[8][2];

#pragma unroll
            for (int mi = 0; mi < 4; mi++) {
                const int r = wm + mi * 16 + a_row;
                const unsigned ad = stb + SWOFF(r, ca);
                asm volatile("ldmatrix.sync.aligned.m8n8.x4.shared.b16 {%0,%1,%2,%3}, [%4];"
                    : "=r"(fAh[mi][0]), "=r"(fAh[mi][1]), "=r"(fAh[mi][2]), "=r"(fAh[mi][3])
                    : "r"(ad));
                asm volatile("ldmatrix.sync.aligned.m8n8.x4.shared.b16 {%0,%1,%2,%3}, [%4];"
                    : "=r"(fAl[mi][0]), "=r"(fAl[mi][1]), "=r"(fAl[mi][2]), "=r"(fAl[mi][3])
                    : "r"(ad + TILEA));
            }
#pragma unroll
            for (int p = 0; p < 4; p++) {
                const int r = wn + p * 16 + b_row;
                const unsigned bd = stb + 2u * TILEA + SWOFF(r, cb);
                asm volatile("ldmatrix.sync.aligned.m8n8.x4.shared.b16 {%0,%1,%2,%3}, [%4];"
                    : "=r"(fBh[2*p][0]), "=r"(fBh[2*p][1]), "=r"(fBh[2*p+1][0]), "=r"(fBh[2*p+1][1])
                    : "r"(bd));
                asm volatile("ldmatrix.sync.aligned.m8n8.x4.shared.b16 {%0,%1,%2,%3}, [%4];"
                    : "=r"(fBl[2*p][0]), "=r"(fBl[2*p][1]), "=r"(fBl[2*p+1][0]), "=r"(fBl[2*p+1][1])
                    : "r"(bd + TILEBB));
            }

#define MMA(d, a, b)                                                           \
    asm volatile("mma.sync.aligned.m16n8k16.row.col.f32.bf16.bf16.f32 "        \
                 "{%0,%1,%2,%3}, {%4,%5,%6,%7}, {%8,%9}, {%0,%1,%2,%3};"       \
                 : "+f"((d)[0]), "+f"((d)[1]), "+f"((d)[2]), "+f"((d)[3])      \
                 : "r"((a)[0]), "r"((a)[1]), "r"((a)[2]), "r"((a)[3]),         \
                   "r"((b)[0]), "r"((b)[1]))

#pragma unroll
            for (int ni = 0; ni < 8; ni++)
#pragma unroll
                for (int mi = 0; mi < 4; mi++)
                    MMA(acc[mi][ni], fAh[mi], fBh[ni]);
#pragma unroll
            for (int ni = 0; ni < 8; ni++)
#pragma unroll
                for (int mi = 0; mi < 4; mi++)
                    MMA(acc[mi][ni], fAh[mi], fBl[ni]);
#pragma unroll
            for (int ni = 0; ni < 8; ni++)
#pragma unroll
                for (int mi = 0; mi < 4; mi++)
                    MMA(acc[mi][ni], fAl[mi], fBh[ni]);
#undef MMA
        }
    }

    // epilogue
#pragma unroll
    for (int mi = 0; mi < 4; mi++) {
        const int row = bm + wm + mi * 16 + g;
#pragma unroll
        for (int ni = 0; ni < 8; ni++) {
            const int col = bn + wn + ni * 8 + tg * 2;
            if (col < N) {
                const float bx = bias[col], by = bias[col + 1];
                float2 v0 = make_float2(acc[mi][ni][0] + bx, acc[mi][ni][1] + by);
                float2 v1 = make_float2(acc[mi][ni][2] + bx, acc[mi][ni][3] + by);
                *(float2*)(C + (size_t)row * N + col)       = v0;
                *(float2*)(C + (size_t)(row + 8) * N + col) = v1;
            }
        }
    }
#undef ISSUE_STAGE
#undef SWOFF
}

// ---------------------------------------------------------------------------
// RoPE, in-place on rows of stride `rstride`, heads at column `coff`.
// ---------------------------------------------------------------------------
__global__ void rope_kernel(float* __restrict__ t, const float* __restrict__ rope,
                            int n_heads, int rstride, int coff)
{
    const int idx = blockIdx.x * blockDim.x + threadIdx.x;
    const int total = SEQ * n_heads * 32;
    if (idx >= total) return;
    const int d = idx & 31;
    const int h = (idx >> 5) % n_heads;
    const int s = idx / (32 * n_heads);

    const float c1 = rope[s * 128 + d];
    const float c2 = rope[s * 128 + d + 32];
    const float s1 = rope[s * 128 + 64 + d];
    const float s2 = rope[s * 128 + 96 + d];

    float* base = t + (size_t)s * rstride + coff + h * HD;
    const float x1 = base[d];
    const float x2 = base[d + 32];
    base[d]      = x1 * c1 - x2 * s1;
    base[d + 32] = x2 * c2 + x1 * s2;
}

// ---------------------------------------------------------------------------
// Sliding-window attention + sink gating. One warp per (query, head).
// q/k/v live in the fused qkv buffer (row stride QKVN).
// ---------------------------------------------------------------------------
__global__ __launch_bounds__(128) void attn_kernel(
    const float* __restrict__ qkv, const float* __restrict__ sinks,
    float* __restrict__ out)
{
    const float scale = 0.16832169945461f;  // (0.1*ln(32)+1)/8
    const int w    = threadIdx.x >> 5;
    const int lane = threadIdx.x & 31;
    const int p = blockIdx.x * 4 + w;
    const int i = p & (SEQ - 1);
    const int h = p >> 11;

    __shared__ float shq[4][64];
    __shared__ float shp[4][128];

    const float* qrow = qkv + (size_t)i * QKVN + h * HD;
    shq[w][lane]      = qrow[lane];
    shq[w][lane + 32] = qrow[lane + 32];
    __syncwarp();

    const int kvh = h >> 3;
    int start = i - (WINDOW - 1); if (start < 0) start = 0;
    const int cnt = i - start + 1;

    float sc[4];
#pragma unroll
    for (int t = 0; t < 4; t++) {
        const int jj = lane + 32 * t;
        if (jj < cnt) {
            const float4* krow =
                (const float4*)(qkv + (size_t)(start + jj) * QKVN + KOFF + kvh * HD);
            float s = 0.f;
#pragma unroll
            for (int d4 = 0; d4 < 16; d4++) {
                const float4 kk = krow[d4];
                s = fmaf(kk.x, shq[w][d4 * 4 + 0], s);
                s = fmaf(kk.y, shq[w][d4 * 4 + 1], s);
                s = fmaf(kk.z, shq[w][d4 * 4 + 2], s);
                s = fmaf(kk.w, shq[w][d4 * 4 + 3], s);
            }
            sc[t] = s * scale;
        } else {
            sc[t] = -1e30f;
        }
    }

    float m = fmaxf(fmaxf(sc[0], sc[1]), fmaxf(sc[2], sc[3]));
#pragma unroll
    for (int o = 16; o; o >>= 1) m = fmaxf(m, __shfl_xor_sync(0xffffffffu, m, o));

    float e[4], sum = 0.f;
#pragma unroll
    for (int t = 0; t < 4; t++) { e[t] = expf(sc[t] - m); sum += e[t]; }
#pragma unroll
    for (int o = 16; o; o >>= 1) sum += __shfl_xor_sync(0xffffffffu, sum, o);

    const float lse  = m + logf(sum);
    const float sig  = 1.f / (1.f + expf(sinks[h] - lse));
    const float wsc  = sig / sum;
#pragma unroll
    for (int t = 0; t < 4; t++) shp[w][lane + 32 * t] = e[t] * wsc;
    __syncwarp();

    float acc0 = 0.f, acc1 = 0.f;
    for (int jj = 0; jj < cnt; jj++) {
        const float pj = shp[w][jj];
        const float* vrow = qkv + (size_t)(start + jj) * QKVN + VOFF + kvh * HD;
        acc0 = fmaf(pj, vrow[lane], acc0);
        acc1 = fmaf(pj, vrow[lane + 32], acc1);
    }
    float* orow = out + (size_t)i * QDIM + h * HD;
    orow[lane]      = acc0;
    orow[lane + 32] = acc1;
}

// ---------------------------------------------------------------------------
extern "C" void kernel_launch(void* const* d_in, const int* in_sizes, int n_in,
                              void* d_out, int out_size)
{
    const float* x     = (const float*)d_in[0];
    const float* rope  = (const float*)d_in[1];
    const float* wq_w  = (const float*)d_in[2];
    const float* wq_b  = (const float*)d_in[3];
    const float* wk_w  = (const float*)d_in[4];
    const float* wk_b  = (const float*)d_in[5];
    const float* wv_w  = (const float*)d_in[6];
    const float* wv_b  = (const float*)d_in[7];
    const float* wo_w  = (const float*)d_in[8];
    const float* wo_b  = (const float*)d_in[9];
    const float* sinks = (const float*)d_in[10];
    float* out = (float*)d_out;

    float *qkv, *attn, *bqkv;
    cudaGetSymbolAddress((void**)&qkv,  g_qkv);
    cudaGetSymbolAddress((void**)&attn, g_attn);
    cudaGetSymbolAddress((void**)&bqkv, g_bqkv);

    bf16 *xh, *xl, *wch, *wcl, *woh, *wol, *ah, *al;
    cudaGetSymbolAddress((void**)&xh, g_xh);   cudaGetSymbolAddress((void**)&xl, g_xl);
    cudaGetSymbolAddress((void**)&wch, g_wch); cudaGetSymbolAddress((void**)&wcl, g_wcl);
    cudaGetSymbolAddress((void**)&woh, g_woh); cudaGetSymbolAddress((void**)&wol, g_wol);
    cudaGetSymbolAddress((void**)&ah, g_ah);   cudaGetSymbolAddress((void**)&al, g_al);

    cudaFuncSetAttribute(gemm_bf16x3, cudaFuncAttributeMaxDynamicSharedMemorySize,
                         GSMEM_BYTES);

    #define SPLIT(src, h_, l_, n) \
        split_bf16<<<((n)/4 + 255)/256, 256>>>(src, h_, l_, n)
    SPLIT(x,    xh,  xl,  SEQ * DIM);
    SPLIT(wq_w, wch,                    wcl,                    QDIM * DIM);
    SPLIT(wk_w, wch + (size_t)KOFF*DIM, wcl + (size_t)KOFF*DIM, KVDIM * DIM);
    SPLIT(wv_w, wch + (size_t)VOFF*DIM, wcl + (size_t)VOFF*DIM, KVDIM * DIM);
    SPLIT(wo_w, woh, wol, DIM * QDIM);
    concat_bias<<<(QKVN + 255) / 256, 256>>>(wq_b, wk_b, wv_b, bqkv);

    // fused QKV projection: [2048 x 5120]
    gemm_bf16x3<<<dim3(QKVN / 256, SEQ / 128), 256, GSMEM_BYTES>>>(
        xh, xl, wch, wcl, bqkv, qkv, SEQ, QKVN, DIM);

    // RoPE on q (64 heads at col 0) and k (8 heads at col 4096)
    rope_kernel<<<(SEQ * NH * 32 + 255) / 256, 256>>>(qkv, rope, NH, QKVN, 0);
    rope_kernel<<<(SEQ * NKV * 32 + 255) / 256, 256>>>(qkv, rope, NKV, QKVN, KOFF);

    // attention
    attn_kernel<<<SEQ * NH / 4, 128>>>(qkv, sinks, attn);

    // split attention output, then O-projection
    SPLIT(attn, ah, al, SEQ * QDIM);
    gemm_bf16x3<<<dim3((DIM + 255) / 256, SEQ / 128), 256, GSMEM_BYTES>>>(
        ah, al, woh, wol, wo_b, out, SEQ, DIM, QDIM);
    #undef SPLIT
}

// round 7
// speedup vs baseline: 1.1476x; 1.1476x over previous
#include <cuda_runtime.h>
#include <cuda_bf16.h>
#include <math.h>

#define SEQ 2048
#define DIM 2880
#define NH 64
#define NKV 8
#define HD 64
#define QDIM (NH*HD)     // 4096
#define KVDIM (NKV*HD)   // 512
#define QKVN 5120        // 4096 + 512 + 512
#define KOFF 4096
#define VOFF 4608
#define WINDOW 128

typedef __nv_bfloat16 bf16;

// fp32 scratch
__device__ float g_qkv[SEQ * QKVN];    // 40 MB: q | k | v per row
__device__ float g_bqkv[QKVN];

// bf16 hi/lo split scratch
__device__ bf16 g_xh[SEQ * DIM],      g_xl[SEQ * DIM];
__device__ bf16 g_wch[QKVN * DIM],    g_wcl[QKVN * DIM];   // concat wq|wk|wv
__device__ bf16 g_woh[DIM * QDIM],    g_wol[DIM * QDIM];
__device__ bf16 g_ah[SEQ * QDIM],     g_al[SEQ * QDIM];    // attn out split

// ---------------------------------------------------------------------------
__global__ void split_bf16(const float* __restrict__ src,
                           bf16* __restrict__ hi, bf16* __restrict__ lo, int n)
{
    int i = (blockIdx.x * blockDim.x + threadIdx.x) * 4;
    if (i >= n) return;
    float4 v = *(const float4*)(src + i);
    bf16 h0 = __float2bfloat16_rn(v.x);
    bf16 h1 = __float2bfloat16_rn(v.y);
    bf16 h2 = __float2bfloat16_rn(v.z);
    bf16 h3 = __float2bfloat16_rn(v.w);
    bf16 l0 = __float2bfloat16_rn(v.x - __bfloat162float(h0));
    bf16 l1 = __float2bfloat16_rn(v.y - __bfloat162float(h1));
    bf16 l2 = __float2bfloat16_rn(v.z - __bfloat162float(h2));
    bf16 l3 = __float2bfloat16_rn(v.w - __bfloat162float(h3));
    __nv_bfloat162* hp = (__nv_bfloat162*)(hi + i);
    __nv_bfloat162* lp = (__nv_bfloat162*)(lo + i);
    hp[0] = __nv_bfloat162(h0, h1); hp[1] = __nv_bfloat162(h2, h3);
    lp[0] = __nv_bfloat162(l0, l1); lp[1] = __nv_bfloat162(l2, l3);
}

__global__ void concat_bias(const float* __restrict__ qb,
                            const float* __restrict__ kb,
                            const float* __restrict__ vb,
                            float* __restrict__ o)
{
    int i = blockIdx.x * blockDim.x + threadIdx.x;
    if (i < KOFF)       o[i] = qb[i];
    else if (i < VOFF)  o[i] = kb[i - KOFF];
    else if (i < QKVN)  o[i] = vb[i - VOFF];
}

// ---------------------------------------------------------------------------
// bf16x3 mma.sync GEMM (NT): C = Ah*Bh^T + Ah*Bl^T + Al*Bh^T + bias
// R4-proven config: block 128x128, BK=32, 3-stage cp.async ring (wait_group 1),
// XOR-swizzled 64B rows, 256 thr = 8 warps (4m x 2n), warp tile 32x64.
// Requires M%128==0, K%32==0; N guarded.
// ---------------------------------------------------------------------------
#define TILEB 8192u                 // one operand tile: 128 rows x 64 bytes
#define STAGEB (4u*TILEB)           // Ah, Al, Bh, Bl = 32 KB
#define NSTG 3
#define GSMEM_BYTES (NSTG*STAGEB)   // 96 KB

__device__ __forceinline__ void cpa16(unsigned dst, const void* src) {
    asm volatile("cp.async.cg.shared.global [%0], [%1], 16;" :: "r"(dst), "l"(src));
}
__device__ __forceinline__ void cpa16p(unsigned dst, const void* src, int sz) {
    asm volatile("cp.async.cg.shared.global [%0], [%1], 16, %2;"
                 :: "r"(dst), "l"(src), "r"(sz));
}

__global__ __launch_bounds__(256) void gemm_bf16x3(
    const bf16* __restrict__ Ah, const bf16* __restrict__ Al,
    const bf16* __restrict__ Bh, const bf16* __restrict__ Bl,
    const float* __restrict__ bias, float* __restrict__ C,
    int M, int N, int K)
{
    extern __shared__ char dsm[];
    unsigned sb;
    { unsigned long long t = __cvta_generic_to_shared(dsm); sb = (unsigned)t; }

    const int tid  = threadIdx.x;
    const int wid  = tid >> 5;
    const int lane = tid & 31;
    const int bm   = blockIdx.y * 128;
    const int bn   = blockIdx.x * 128;
    const int wm   = (wid & 3) * 32;
    const int wn   = (wid >> 2) * 64;
    const int g    = lane >> 2;
    const int tg   = lane & 3;

    const int KT = K / 32;

    const int r0c = tid >> 2;            // rows 0..63 (chunk 0), +64 (chunk 1)
    const int c0c = tid & 3;             // 16B segment 0..3

#define SWOFF(r, c) ((unsigned)((r) * 64 + ((((c) ^ (((r) >> 1) & 3))) << 4)))

#define ISSUE_STAGE(sidx, k0)                                                  \
    do {                                                                       \
        const unsigned tb = sb + (unsigned)(sidx) * STAGEB;                    \
        _Pragma("unroll")                                                      \
        for (int it = 0; it < 2; it++) {                                       \
            const int r = r0c + it * 64;                                       \
            const unsigned so = SWOFF(r, c0c);                                 \
            const size_t ao = (size_t)(bm + r) * K + (k0) + c0c * 8;           \
            const int brw = bn + r;                                            \
            const int pz  = (brw < N) ? 16 : 0;                                \
            const size_t bo = (size_t)((brw < N) ? brw : 0) * K + (k0) + c0c * 8; \
            cpa16 (tb + so,             Ah + ao);                              \
            cpa16 (tb + TILEB + so,     Al + ao);                              \
            cpa16p(tb + 2 * TILEB + so, Bh + bo, pz);                          \
            cpa16p(tb + 3 * TILEB + so, Bl + bo, pz);                          \
        }                                                                      \
        asm volatile("cp.async.commit_group;");                                \
    } while (0)

    float acc[2][8][4];
#pragma unroll
    for (int mi = 0; mi < 2; mi++)
#pragma unroll
        for (int ni = 0; ni < 8; ni++)
#pragma unroll
            for (int r = 0; r < 4; r++) acc[mi][ni][r] = 0.f;

    ISSUE_STAGE(0, 0);
    ISSUE_STAGE(1, 32);

    const int a_row = ((lane >> 3) & 1) * 8 + (lane & 7);
    const int a_ch  = (lane >> 4) & 1;
    const int b_row = ((lane >> 4) & 1) * 8 + (lane & 7);
    const int b_ch  = (lane >> 3) & 1;

    for (int kt = 0; kt < KT; kt++) {
        asm volatile("cp.async.wait_group %0;" :: "n"(1));
        __syncthreads();

        if (kt + 2 < KT) ISSUE_STAGE((kt + 2) % NSTG, (kt + 2) * 32);
        else             asm volatile("cp.async.commit_group;");

        const unsigned stb = sb + (unsigned)(kt % NSTG) * STAGEB;

#pragma unroll
        for (int ks = 0; ks < 2; ks++) {
            unsigned fAh[2][4], fAl[2][4], fBh[8][2], fBl[8][2];
            const int ca = ks * 2 + a_ch;
            const int cb = ks * 2 + b_ch;

#pragma unroll
            for (int mi = 0; mi < 2; mi++) {
                const int r = wm + mi * 16 + a_row;
                const unsigned ad = stb + SWOFF(r, ca);
                asm volatile("ldmatrix.sync.aligned.m8n8.x4.shared.b16 {%0,%1,%2,%3}, [%4];"
                    : "=r"(fAh[mi][0]), "=r"(fAh[mi][1]), "=r"(fAh[mi][2]), "=r"(fAh[mi][3])
                    : "r"(ad));
                asm volatile("ldmatrix.sync.aligned.m8n8.x4.shared.b16 {%0,%1,%2,%3}, [%4];"
                    : "=r"(fAl[mi][0]), "=r"(fAl[mi][1]), "=r"(fAl[mi][2]), "=r"(fAl[mi][3])
                    : "r"(ad + TILEB));
            }
#pragma unroll
            for (int p = 0; p < 4; p++) {
                const int r = wn + p * 16 + b_row;
                const unsigned bd = stb + 2u * TILEB + SWOFF(r, cb);
                asm volatile("ldmatrix.sync.aligned.m8n8.x4.shared.b16 {%0,%1,%2,%3}, [%4];"
                    : "=r"(fBh[2*p][0]), "=r"(fBh[2*p][1]), "=r"(fBh[2*p+1][0]), "=r"(fBh[2*p+1][1])
                    : "r"(bd));
                asm volatile("ldmatrix.sync.aligned.m8n8.x4.shared.b16 {%0,%1,%2,%3}, [%4];"
                    : "=r"(fBl[2*p][0]), "=r"(fBl[2*p][1]), "=r"(fBl[2*p+1][0]), "=r"(fBl[2*p+1][1])
                    : "r"(bd + TILEB));
            }

#define MMA(d, a, b)                                                           \
    asm volatile("mma.sync.aligned.m16n8k16.row.col.f32.bf16.bf16.f32 "        \
                 "{%0,%1,%2,%3}, {%4,%5,%6,%7}, {%8,%9}, {%0,%1,%2,%3};"       \
                 : "+f"((d)[0]), "+f"((d)[1]), "+f"((d)[2]), "+f"((d)[3])      \
                 : "r"((a)[0]), "r"((a)[1]), "r"((a)[2]), "r"((a)[3]),         \
                   "r"((b)[0]), "r"((b)[1]))

#pragma unroll
            for (int ni = 0; ni < 8; ni++)
#pragma unroll
                for (int mi = 0; mi < 2; mi++)
                    MMA(acc[mi][ni], fAh[mi], fBh[ni]);
#pragma unroll
            for (int ni = 0; ni < 8; ni++)
#pragma unroll
                for (int mi = 0; mi < 2; mi++)
                    MMA(acc[mi][ni], fAh[mi], fBl[ni]);
#pragma unroll
            for (int ni = 0; ni < 8; ni++)
#pragma unroll
                for (int mi = 0; mi < 2; mi++)
                    MMA(acc[mi][ni], fAl[mi], fBh[ni]);
#undef MMA
        }
    }

    // epilogue
#pragma unroll
    for (int mi = 0; mi < 2; mi++) {
        const int row = bm + wm + mi * 16 + g;
#pragma unroll
        for (int ni = 0; ni < 8; ni++) {
            const int col = bn + wn + ni * 8 + tg * 2;
            if (col < N) {
                const float bx = bias[col], by = bias[col + 1];
                float2 v0 = make_float2(acc[mi][ni][0] + bx, acc[mi][ni][1] + by);
                float2 v1 = make_float2(acc[mi][ni][2] + bx, acc[mi][ni][3] + by);
                *(float2*)(C + (size_t)row * N + col)       = v0;
                *(float2*)(C + (size_t)(row + 8) * N + col) = v1;
            }
        }
    }
#undef ISSUE_STAGE
#undef SWOFF
}

// ---------------------------------------------------------------------------
// RoPE, in-place on rows of stride `rstride`, heads at column `coff`.
// ---------------------------------------------------------------------------
__global__ void rope_kernel(float* __restrict__ t, const float* __restrict__ rope,
                            int n_heads, int rstride, int coff)
{
    const int idx = blockIdx.x * blockDim.x + threadIdx.x;
    const int total = SEQ * n_heads * 32;
    if (idx >= total) return;
    const int d = idx & 31;
    const int h = (idx >> 5) % n_heads;
    const int s = idx / (32 * n_heads);

    const float c1 = rope[s * 128 + d];
    const float c2 = rope[s * 128 + d + 32];
    const float s1 = rope[s * 128 + 64 + d];
    const float s2 = rope[s * 128 + 96 + d];

    float* base = t + (size_t)s * rstride + coff + h * HD;
    const float x1 = base[d];
    const float x2 = base[d + 32];
    base[d]      = x1 * c1 - x2 * s1;
    base[d + 32] = x2 * c2 + x1 * s2;
}

// ---------------------------------------------------------------------------
// Sliding-window attention + sink gating. One warp per (query, head).
// Writes bf16 hi/lo split of the output directly (feeds O-proj GEMM).
// ---------------------------------------------------------------------------
__global__ __launch_bounds__(128) void attn_kernel(
    const float* __restrict__ qkv, const float* __restrict__ sinks,
    bf16* __restrict__ oh, bf16* __restrict__ ol)
{
    const float scale = 0.16832169945461f;  // (0.1*ln(32)+1)/8
    const int w    = threadIdx.x >> 5;
    const int lane = threadIdx.x & 31;
    const int p = blockIdx.x * 4 + w;
    const int i = p & (SEQ - 1);
    const int h = p >> 11;

    __shared__ float shq[4][64];
    __shared__ float shp[4][128];

    const float* qrow = qkv + (size_t)i * QKVN + h * HD;
    shq[w][lane]      = qrow[lane];
    shq[w][lane + 32] = qrow[lane + 32];
    __syncwarp();

    const int kvh = h >> 3;
    int start = i - (WINDOW - 1); if (start < 0) start = 0;
    const int cnt = i - start + 1;

    float sc[4];
#pragma unroll
    for (int t = 0; t < 4; t++) {
        const int jj = lane + 32 * t;
        if (jj < cnt) {
            const float4* krow =
                (const float4*)(qkv + (size_t)(start + jj) * QKVN + KOFF + kvh * HD);
            float s = 0.f;
#pragma unroll
            for (int d4 = 0; d4 < 16; d4++) {
                const float4 kk = krow[d4];
                s = fmaf(kk.x, shq[w][d4 * 4 + 0], s);
                s = fmaf(kk.y, shq[w][d4 * 4 + 1], s);
                s = fmaf(kk.z, shq[w][d4 * 4 + 2], s);
                s = fmaf(kk.w, shq[w][d4 * 4 + 3], s);
            }
            sc[t] = s * scale;
        } else {
            sc[t] = -1e30f;
        }
    }

    float m = fmaxf(fmaxf(sc[0], sc[1]), fmaxf(sc[2], sc[3]));
#pragma unroll
    for (int o = 16; o; o >>= 1) m = fmaxf(m, __shfl_xor_sync(0xffffffffu, m, o));

    float e[4], sum = 0.f;
#pragma unroll
    for (int t = 0; t < 4; t++) { e[t] = expf(sc[t] - m); sum += e[t]; }
#pragma unroll
    for (int o = 16; o; o >>= 1) sum += __shfl_xor_sync(0xffffffffu, sum, o);

    const float lse  = m + logf(sum);
    const float sig  = 1.f / (1.f + expf(sinks[h] - lse));
    const float wsc  = sig / sum;
#pragma unroll
    for (int t = 0; t < 4; t++) shp[w][lane + 32 * t] = e[t] * wsc;
    __syncwarp();

    float acc0 = 0.f, acc1 = 0.f;
    for (int jj = 0; jj < cnt; jj++) {
        const float pj = shp[w][jj];
        const float* vrow = qkv + (size_t)(start + jj) * QKVN + VOFF + kvh * HD;
        acc0 = fmaf(pj, vrow[lane], acc0);
        acc1 = fmaf(pj, vrow[lane + 32], acc1);
    }

    const size_t ob = (size_t)i * QDIM + h * HD;
    bf16 h0 = __float2bfloat16_rn(acc0);
    bf16 h1 = __float2bfloat16_rn(acc1);
    oh[ob + lane]      = h0;
    oh[ob + lane + 32] = h1;
    ol[ob + lane]      = __float2bfloat16_rn(acc0 - __bfloat162float(h0));
    ol[ob + lane + 32] = __float2bfloat16_rn(acc1 - __bfloat162float(h1));
}

// ---------------------------------------------------------------------------
extern "C" void kernel_launch(void* const* d_in, const int* in_sizes, int n_in,
                              void* d_out, int out_size)
{
    const float* x     = (const float*)d_in[0];
    const float* rope  = (const float*)d_in[1];
    const float* wq_w  = (const float*)d_in[2];
    const float* wq_b  = (const float*)d_in[3];
    const float* wk_w  = (const float*)d_in[4];
    const float* wk_b  = (const float*)d_in[5];
    const float* wv_w  = (const float*)d_in[6];
    const float* wv_b  = (const float*)d_in[7];
    const float* wo_w  = (const float*)d_in[8];
    const float* wo_b  = (const float*)d_in[9];
    const float* sinks = (const float*)d_in[10];
    float* out = (float*)d_out;

    float *qkv, *bqkv;
    cudaGetSymbolAddress((void**)&qkv,  g_qkv);
    cudaGetSymbolAddress((void**)&bqkv, g_bqkv);

    bf16 *xh, *xl, *wch, *wcl, *woh, *wol, *ah, *al;
    cudaGetSymbolAddress((void**)&xh, g_xh);   cudaGetSymbolAddress((void**)&xl, g_xl);
    cudaGetSymbolAddress((void**)&wch, g_wch); cudaGetSymbolAddress((void**)&wcl, g_wcl);
    cudaGetSymbolAddress((void**)&woh, g_woh); cudaGetSymbolAddress((void**)&wol, g_wol);
    cudaGetSymbolAddress((void**)&ah, g_ah);   cudaGetSymbolAddress((void**)&al, g_al);

    cudaFuncSetAttribute(gemm_bf16x3, cudaFuncAttributeMaxDynamicSharedMemorySize,
                         GSMEM_BYTES);

    #define SPLIT(src, h_, l_, n) \
        split_bf16<<<((n)/4 + 255)/256, 256>>>(src, h_, l_, n)
    SPLIT(x,    xh,  xl,  SEQ * DIM);
    SPLIT(wq_w, wch,                    wcl,                    QDIM * DIM);
    SPLIT(wk_w, wch + (size_t)KOFF*DIM, wcl + (size_t)KOFF*DIM, KVDIM * DIM);
    SPLIT(wv_w, wch + (size_t)VOFF*DIM, wcl + (size_t)VOFF*DIM, KVDIM * DIM);
    SPLIT(wo_w, woh, wol, DIM * QDIM);
    concat_bias<<<(QKVN + 255) / 256, 256>>>(wq_b, wk_b, wv_b, bqkv);

    // fused QKV projection: [2048 x 5120], 640 CTAs
    gemm_bf16x3<<<dim3(QKVN / 128, SEQ / 128), 256, GSMEM_BYTES>>>(
        xh, xl, wch, wcl, bqkv, qkv, SEQ, QKVN, DIM);

    // RoPE on q (64 heads at col 0) and k (8 heads at col 4096)
    rope_kernel<<<(SEQ * NH * 32 + 255) / 256, 256>>>(qkv, rope, NH, QKVN, 0);
    rope_kernel<<<(SEQ * NKV * 32 + 255) / 256, 256>>>(qkv, rope, NKV, QKVN, KOFF);

    // attention (writes bf16 hi/lo split directly)
    attn_kernel<<<SEQ * NH / 4, 128>>>(qkv, sinks, ah, al);

    // O-projection
    gemm_bf16x3<<<dim3((DIM + 127) / 128, SEQ / 128), 256, GSMEM_BYTES>>>(
        ah, al, woh, wol, wo_b, out, SEQ, DIM, QDIM);
    #undef SPLIT
}

// round 8
// speedup vs baseline: 1.3229x; 1.1527x over previous
#include <cuda_runtime.h>
#include <cuda_fp16.h>
#include <math.h>

#define SEQ 2048
#define DIM 2880
#define NH 64
#define NKV 8
#define HD 64
#define QDIM (NH*HD)     // 4096
#define KVDIM (NKV*HD)   // 512
#define QKVN 5120        // 4096 + 512 + 512
#define KOFF 4096
#define VOFF 4608
#define WINDOW 128

typedef __half f16;

// fp32 scratch
__device__ float g_qkv[SEQ * QKVN];    // 40 MB: q | k | v per row
__device__ float g_bqkv[QKVN];

// fp16 operand scratch
__device__ f16 g_xh[SEQ * DIM],  g_xl[SEQ * DIM];     // x split hi/lo
__device__ f16 g_wc[QKVN * DIM];                      // concat wq|wk|wv (plain fp16)
__device__ f16 g_wo[DIM * QDIM];                      // wo (plain fp16)
__device__ f16 g_ah[SEQ * QDIM], g_al[SEQ * QDIM];    // attn out split hi/lo

// ---------------------------------------------------------------------------
// split fp32 -> fp16 hi + fp16 lo (8 elems/thread, 16B stores)
// ---------------------------------------------------------------------------
__global__ void split_f16(const float* __restrict__ src,
                          f16* __restrict__ hi, f16* __restrict__ lo, int n)
{
    int i = (blockIdx.x * blockDim.x + threadIdx.x) * 8;
    if (i >= n) return;
    float4 a = *(const float4*)(src + i);
    float4 b = *(const float4*)(src + i + 4);
    float v[8] = {a.x, a.y, a.z, a.w, b.x, b.y, b.z, b.w};
    __half2 hh[4], ll[4];
#pragma unroll
    for (int j = 0; j < 4; j++) {
        f16 h0 = __float2half_rn(v[2*j]);
        f16 h1 = __float2half_rn(v[2*j+1]);
        hh[j] = __halves2half2(h0, h1);
        ll[j] = __halves2half2(__float2half_rn(v[2*j]   - __half2float(h0)),
                               __float2half_rn(v[2*j+1] - __half2float(h1)));
    }
    *(uint4*)(hi + i) = *(uint4*)hh;
    *(uint4*)(lo + i) = *(uint4*)ll;
}

// plain fp32 -> fp16 convert (8 elems/thread)
__global__ void conv_f16(const float* __restrict__ src, f16* __restrict__ dst, int n)
{
    int i = (blockIdx.x * blockDim.x + threadIdx.x) * 8;
    if (i >= n) return;
    float4 a = *(const float4*)(src + i);
    float4 b = *(const float4*)(src + i + 4);
    __half2 hh[4];
    hh[0] = __halves2half2(__float2half_rn(a.x), __float2half_rn(a.y));
    hh[1] = __halves2half2(__float2half_rn(a.z), __float2half_rn(a.w));
    hh[2] = __halves2half2(__float2half_rn(b.x), __float2half_rn(b.y));
    hh[3] = __halves2half2(__float2half_rn(b.z), __float2half_rn(b.w));
    *(uint4*)(dst + i) = *(uint4*)hh;
}

__global__ void concat_bias(const float* __restrict__ qb,
                            const float* __restrict__ kb,
                            const float* __restrict__ vb,
                            float* __restrict__ o)
{
    int i = blockIdx.x * blockDim.x + threadIdx.x;
    if (i < KOFF)       o[i] = qb[i];
    else if (i < VOFF)  o[i] = kb[i - KOFF];
    else if (i < QKVN)  o[i] = vb[i - VOFF];
}

// ---------------------------------------------------------------------------
// fp16x2 mma.sync GEMM (NT): C = Ah*B^T + Al*B^T + bias
// A split fp16 hi/lo (exact to ~2^-22), B plain fp16 (error ~2^-12).
// Block 128x128, BK=32, 3-stage cp.async ring (wait_group 1), XOR-swizzled
// 64B rows, 256 thr = 8 warps (4m x 2n), warp tile 32x64.
// Requires M%128==0, K%32==0; N guarded.
// ---------------------------------------------------------------------------
#define TILEB 8192u                 // one operand tile: 128 rows x 64 bytes
#define STAGEB (3u*TILEB)           // Ah, Al, B = 24 KB
#define NSTG 3
#define GSMEM_BYTES (NSTG*STAGEB)   // 72 KB

__device__ __forceinline__ void cpa16(unsigned dst, const void* src) {
    asm volatile("cp.async.cg.shared.global [%0], [%1], 16;" :: "r"(dst), "l"(src));
}
__device__ __forceinline__ void cpa16p(unsigned dst, const void* src, int sz) {
    asm volatile("cp.async.cg.shared.global [%0], [%1], 16, %2;"
                 :: "r"(dst), "l"(src), "r"(sz));
}

__global__ __launch_bounds__(256) void gemm_f16x2(
    const f16* __restrict__ Ah, const f16* __restrict__ Al,
    const f16* __restrict__ B,
    const float* __restrict__ bias, float* __restrict__ C,
    int M, int N, int K)
{
    extern __shared__ char dsm[];
    unsigned sb;
    { unsigned long long t = __cvta_generic_to_shared(dsm); sb = (unsigned)t; }

    const int tid  = threadIdx.x;
    const int wid  = tid >> 5;
    const int lane = tid & 31;
    const int bm   = blockIdx.y * 128;
    const int bn   = blockIdx.x * 128;
    const int wm   = (wid & 3) * 32;
    const int wn   = (wid >> 2) * 64;
    const int g    = lane >> 2;
    const int tg   = lane & 3;

    const int KT = K / 32;

    const int r0c = tid >> 2;            // rows 0..63 (chunk 0), +64 (chunk 1)
    const int c0c = tid & 3;             // 16B segment 0..3

#define SWOFF(r, c) ((unsigned)((r) * 64 + ((((c) ^ (((r) >> 1) & 3))) << 4)))

#define ISSUE_STAGE(sidx, k0)                                                  \
    do {                                                                       \
        const unsigned tb = sb + (unsigned)(sidx) * STAGEB;                    \
        _Pragma("unroll")                                                      \
        for (int it = 0; it < 2; it++) {                                       \
            const int r = r0c + it * 64;                                       \
            const unsigned so = SWOFF(r, c0c);                                 \
            const size_t ao = (size_t)(bm + r) * K + (k0) + c0c * 8;           \
            const int brw = bn + r;                                            \
            const int pz  = (brw < N) ? 16 : 0;                                \
            const size_t bo = (size_t)((brw < N) ? brw : 0) * K + (k0) + c0c * 8; \
            cpa16 (tb + so,             Ah + ao);                              \
            cpa16 (tb + TILEB + so,     Al + ao);                              \
            cpa16p(tb + 2 * TILEB + so, B + bo, pz);                           \
        }                                                                      \
        asm volatile("cp.async.commit_group;");                                \
    } while (0)

    float acc[2][8][4];
#pragma unroll
    for (int mi = 0; mi < 2; mi++)
#pragma unroll
        for (int ni = 0; ni < 8; ni++)
#pragma unroll
            for (int r = 0; r < 4; r++) acc[mi][ni][r] = 0.f;

    ISSUE_STAGE(0, 0);
    ISSUE_STAGE(1, 32);

    const int a_row = ((lane >> 3) & 1) * 8 + (lane & 7);
    const int a_ch  = (lane >> 4) & 1;
    const int b_row = ((lane >> 4) & 1) * 8 + (lane & 7);
    const int b_ch  = (lane >> 3) & 1;

    for (int kt = 0; kt < KT; kt++) {
        asm volatile("cp.async.wait_group %0;" :: "n"(1));
        __syncthreads();

        if (kt + 2 < KT) ISSUE_STAGE((kt + 2) % NSTG, (kt + 2) * 32);
        else             asm volatile("cp.async.commit_group;");

        const unsigned stb = sb + (unsigned)(kt % NSTG) * STAGEB;

#pragma unroll
        for (int ks = 0; ks < 2; ks++) {
            unsigned fAh[2][4], fAl[2][4], fB[8][2];
            const int ca = ks * 2 + a_ch;
            const int cb = ks * 2 + b_ch;

#pragma unroll
            for (int mi = 0; mi < 2; mi++) {
                const int r = wm + mi * 16 + a_row;
                const unsigned ad = stb + SWOFF(r, ca);
                asm volatile("ldmatrix.sync.aligned.m8n8.x4.shared.b16 {%0,%1,%2,%3}, [%4];"
                    : "=r"(fAh[mi][0]), "=r"(fAh[mi][1]), "=r"(fAh[mi][2]), "=r"(fAh[mi][3])
                    : "r"(ad));
                asm volatile("ldmatrix.sync.aligned.m8n8.x4.shared.b16 {%0,%1,%2,%3}, [%4];"
                    : "=r"(fAl[mi][0]), "=r"(fAl[mi][1]), "=r"(fAl[mi][2]), "=r"(fAl[mi][3])
                    : "r"(ad + TILEB));
            }
#pragma unroll
            for (int p = 0; p < 4; p++) {
                const int r = wn + p * 16 + b_row;
                const unsigned bd = stb + 2u * TILEB + SWOFF(r, cb);
                asm volatile("ldmatrix.sync.aligned.m8n8.x4.shared.b16 {%0,%1,%2,%3}, [%4];"
                    : "=r"(fB[2*p][0]), "=r"(fB[2*p][1]), "=r"(fB[2*p+1][0]), "=r"(fB[2*p+1][1])
                    : "r"(bd));
            }

#define MMA(d, a, b)                                                           \
    asm volatile("mma.sync.aligned.m16n8k16.row.col.f32.f16.f16.f32 "          \
                 "{%0,%1,%2,%3}, {%4,%5,%6,%7}, {%8,%9}, {%0,%1,%2,%3};"       \
                 : "+f"((d)[0]), "+f"((d)[1]), "+f"((d)[2]), "+f"((d)[3])      \
                 : "r"((a)[0]), "r"((a)[1]), "r"((a)[2]), "r"((a)[3]),         \
                   "r"((b)[0]), "r"((b)[1]))

#pragma unroll
            for (int ni = 0; ni < 8; ni++)
#pragma unroll
                for (int mi = 0; mi < 2; mi++)
                    MMA(acc[mi][ni], fAh[mi], fB[ni]);
#pragma unroll
            for (int ni = 0; ni < 8; ni++)
#pragma unroll
                for (int mi = 0; mi < 2; mi++)
                    MMA(acc[mi][ni], fAl[mi], fB[ni]);
#undef MMA
        }
    }

    // epilogue
#pragma unroll
    for (int mi = 0; mi < 2; mi++) {
        const int row = bm + wm + mi * 16 + g;
#pragma unroll
        for (int ni = 0; ni < 8; ni++) {
            const int col = bn + wn + ni * 8 + tg * 2;
            if (col < N) {
                const float bx = bias[col], by = bias[col + 1];
                float2 v0 = make_float2(acc[mi][ni][0] + bx, acc[mi][ni][1] + by);
                float2 v1 = make_float2(acc[mi][ni][2] + bx, acc[mi][ni][3] + by);
                *(float2*)(C + (size_t)row * N + col)       = v0;
                *(float2*)(C + (size_t)(row + 8) * N + col) = v1;
            }
        }
    }
#undef ISSUE_STAGE
#undef SWOFF
}

// ---------------------------------------------------------------------------
// RoPE, in-place on rows of stride `rstride`, heads at column `coff`.
// ---------------------------------------------------------------------------
__global__ void rope_kernel(float* __restrict__ t, const float* __restrict__ rope,
                            int n_heads, int rstride, int coff)
{
    const int idx = blockIdx.x * blockDim.x + threadIdx.x;
    const int total = SEQ * n_heads * 32;
    if (idx >= total) return;
    const int d = idx & 31;
    const int h = (idx >> 5) % n_heads;
    const int s = idx / (32 * n_heads);

    const float c1 = rope[s * 128 + d];
    const float c2 = rope[s * 128 + d + 32];
    const float s1 = rope[s * 128 + 64 + d];
    const float s2 = rope[s * 128 + 96 + d];

    float* base = t + (size_t)s * rstride + coff + h * HD;
    const float x1 = base[d];
    const float x2 = base[d + 32];
    base[d]      = x1 * c1 - x2 * s1;
    base[d + 32] = x2 * c2 + x1 * s2;
}

// ---------------------------------------------------------------------------
// Sliding-window attention + sink gating. One warp per (query, head).
// Writes fp16 hi/lo split of the output directly (feeds O-proj GEMM).
// ---------------------------------------------------------------------------
__global__ __launch_bounds__(128) void attn_kernel(
    const float* __restrict__ qkv, const float* __restrict__ sinks,
    f16* __restrict__ oh, f16* __restrict__ ol)
{
    const float scale = 0.16832169945461f;  // (0.1*ln(32)+1)/8
    const int w    = threadIdx.x >> 5;
    const int lane = threadIdx.x & 31;
    const int p = blockIdx.x * 4 + w;
    const int i = p & (SEQ - 1);
    const int h = p >> 11;

    __shared__ float shq[4][64];
    __shared__ float shp[4][128];

    const float* qrow = qkv + (size_t)i * QKVN + h * HD;
    shq[w][lane]      = qrow[lane];
    shq[w][lane + 32] = qrow[lane + 32];
    __syncwarp();

    const int kvh = h >> 3;
    int start = i - (WINDOW - 1); if (start < 0) start = 0;
    const int cnt = i - start + 1;

    float sc[4];
#pragma unroll
    for (int t = 0; t < 4; t++) {
        const int jj = lane + 32 * t;
        if (jj < cnt) {
            const float4* krow =
                (const float4*)(qkv + (size_t)(start + jj) * QKVN + KOFF + kvh * HD);
            float s = 0.f;
#pragma unroll
            for (int d4 = 0; d4 < 16; d4++) {
                const float4 kk = krow[d4];
                s = fmaf(kk.x, shq[w][d4 * 4 + 0], s);
                s = fmaf(kk.y, shq[w][d4 * 4 + 1], s);
                s = fmaf(kk.z, shq[w][d4 * 4 + 2], s);
                s = fmaf(kk.w, shq[w][d4 * 4 + 3], s);
            }
            sc[t] = s * scale;
        } else {
            sc[t] = -1e30f;
        }
    }

    float m = fmaxf(fmaxf(sc[0], sc[1]), fmaxf(sc[2], sc[3]));
#pragma unroll
    for (int o = 16; o; o >>= 1) m = fmaxf(m, __shfl_xor_sync(0xffffffffu, m, o));

    float e[4], sum = 0.f;
#pragma unroll
    for (int t = 0; t < 4; t++) { e[t] = expf(sc[t] - m); sum += e[t]; }
#pragma unroll
    for (int o = 16; o; o >>= 1) sum += __shfl_xor_sync(0xffffffffu, sum, o);

    const float lse  = m + logf(sum);
    const float sig  = 1.f / (1.f + expf(sinks[h] - lse));
    const float wsc  = sig / sum;
#pragma unroll
    for (int t = 0; t < 4; t++) shp[w][lane + 32 * t] = e[t] * wsc;
    __syncwarp();

    float acc0 = 0.f, acc1 = 0.f;
    for (int jj = 0; jj < cnt; jj++) {
        const float pj = shp[w][jj];
        const float* vrow = qkv + (size_t)(start + jj) * QKVN + VOFF + kvh * HD;
        acc0 = fmaf(pj, vrow[lane], acc0);
        acc1 = fmaf(pj, vrow[lane + 32], acc1);
    }

    const size_t ob = (size_t)i * QDIM + h * HD;
    f16 h0 = __float2half_rn(acc0);
    f16 h1 = __float2half_rn(acc1);
    oh[ob + lane]      = h0;
    oh[ob + lane + 32] = h1;
    ol[ob + lane]      = __float2half_rn(acc0 - __half2float(h0));
    ol[ob + lane + 32] = __float2half_rn(acc1 - __half2float(h1));
}

// ---------------------------------------------------------------------------
extern "C" void kernel_launch(void* const* d_in, const int* in_sizes, int n_in,
                              void* d_out, int out_size)
{
    const float* x     = (const float*)d_in[0];
    const float* rope  = (const float*)d_in[1];
    const float* wq_w  = (const float*)d_in[2];
    const float* wq_b  = (const float*)d_in[3];
    const float* wk_w  = (const float*)d_in[4];
    const float* wk_b  = (const float*)d_in[5];
    const float* wv_w  = (const float*)d_in[6];
    const float* wv_b  = (const float*)d_in[7];
    const float* wo_w  = (const float*)d_in[8];
    const float* wo_b  = (const float*)d_in[9];
    const float* sinks = (const float*)d_in[10];
    float* out = (float*)d_out;

    float *qkv, *bqkv;
    cudaGetSymbolAddress((void**)&qkv,  g_qkv);
    cudaGetSymbolAddress((void**)&bqkv, g_bqkv);

    f16 *xh, *xl, *wc, *wo, *ah, *al;
    cudaGetSymbolAddress((void**)&xh, g_xh); cudaGetSymbolAddress((void**)&xl, g_xl);
    cudaGetSymbolAddress((void**)&wc, g_wc); cudaGetSymbolAddress((void**)&wo, g_wo);
    cudaGetSymbolAddress((void**)&ah, g_ah); cudaGetSymbolAddress((void**)&al, g_al);

    cudaFuncSetAttribute(gemm_f16x2, cudaFuncAttributeMaxDynamicSharedMemorySize,
                         GSMEM_BYTES);

    // x split (hi/lo), weights plain fp16
    split_f16<<<(SEQ * DIM / 8 + 255) / 256, 256>>>(x, xh, xl, SEQ * DIM);
    conv_f16<<<(QDIM * DIM / 8 + 255) / 256, 256>>>(wq_w, wc, QDIM * DIM);
    conv_f16<<<(KVDIM * DIM / 8 + 255) / 256, 256>>>(wk_w, wc + (size_t)KOFF * DIM, KVDIM * DIM);
    conv_f16<<<(KVDIM * DIM / 8 + 255) / 256, 256>>>(wv_w, wc + (size_t)VOFF * DIM, KVDIM * DIM);
    conv_f16<<<(DIM * QDIM / 8 + 255) / 256, 256>>>(wo_w, wo, DIM * QDIM);
    concat_bias<<<(QKVN + 255) / 256, 256>>>(wq_b, wk_b, wv_b, bqkv);

    // fused QKV projection: [2048 x 5120], 640 CTAs
    gemm_f16x2<<<dim3(QKVN / 128, SEQ / 128), 256, GSMEM_BYTES>>>(
        xh, xl, wc, bqkv, qkv, SEQ, QKVN, DIM);

    // RoPE on q (64 heads at col 0) and k (8 heads at col 4096)
    rope_kernel<<<(SEQ * NH * 32 + 255) / 256, 256>>>(qkv, rope, NH, QKVN, 0);
    rope_kernel<<<(SEQ * NKV * 32 + 255) / 256, 256>>>(qkv, rope, NKV, QKVN, KOFF);

    // attention (writes fp16 hi/lo split directly)
    attn_kernel<<<SEQ * NH / 4, 128>>>(qkv, sinks, ah, al);

    // O-projection
    gemm_f16x2<<<dim3((DIM + 127) / 128, SEQ / 128), 256, GSMEM_BYTES>>>(
        ah, al, wo, wo_b, out, SEQ, DIM, QDIM);
}

// round 9
// speedup vs baseline: 1.3426x; 1.0149x over previous
#include <cuda_runtime.h>
#include <cuda_fp16.h>
#include <math.h>

#define SEQ 2048
#define DIM 2880
#define NH 64
#define NKV 8
#define HD 64
#define QDIM (NH*HD)     // 4096
#define KVDIM (NKV*HD)   // 512
#define QKVN 5120        // 4096 + 512 + 512
#define KOFF 4096
#define VOFF 4608
#define WINDOW 128

typedef __half f16;

// fp32 scratch
__device__ float g_qkv[SEQ * QKVN];    // 40 MB: q | k | v per row
__device__ float g_bqkv[QKVN];

// fp16 operand scratch
__device__ f16 g_xh[SEQ * DIM],  g_xl[SEQ * DIM];     // x split hi/lo
__device__ f16 g_wc[QKVN * DIM];                      // concat wq|wk|wv (fp16)
__device__ f16 g_wo[DIM * QDIM];                      // wo (fp16)
__device__ f16 g_ah[SEQ * QDIM], g_al[SEQ * QDIM];    // attn out split hi/lo

// ---------------------------------------------------------------------------
// Fused prep: x hi/lo split, wq/wk/wv -> wc fp16, wo -> fp16, bias concat.
// One launch; each thread processes 8 contiguous elements of one region.
// ---------------------------------------------------------------------------
#define R0 (SEQ*DIM/8)          // x split
#define R1 (QDIM*DIM/8)         // wq
#define R2 (KVDIM*DIM/8)        // wk
#define R3 (KVDIM*DIM/8)        // wv
#define R4 ((size_t)DIM*QDIM/8) // wo
#define R5 (QKVN/8)             // bias concat
#define PREP_THREADS (R0+R1+R2+R3+R4+R5)

__device__ __forceinline__ void conv8(const float* __restrict__ s, f16* __restrict__ d) {
    float4 a = *(const float4*)s;
    float4 b = *(const float4*)(s + 4);
    __half2 hh[4];
    hh[0] = __halves2half2(__float2half_rn(a.x), __float2half_rn(a.y));
    hh[1] = __halves2half2(__float2half_rn(a.z), __float2half_rn(a.w));
    hh[2] = __halves2half2(__float2half_rn(b.x), __float2half_rn(b.y));
    hh[3] = __halves2half2(__float2half_rn(b.z), __float2half_rn(b.w));
    *(uint4*)d = *(uint4*)hh;
}

__global__ void prep(const float* __restrict__ x,
                     const float* __restrict__ wq, const float* __restrict__ wk,
                     const float* __restrict__ wv, const float* __restrict__ wo,
                     const float* __restrict__ qb, const float* __restrict__ kb,
                     const float* __restrict__ vb,
                     f16* __restrict__ xh, f16* __restrict__ xl,
                     f16* __restrict__ wc, f16* __restrict__ wo16,
                     float* __restrict__ bqkv)
{
    long t = (long)blockIdx.x * blockDim.x + threadIdx.x;
    if (t < (long)R0) {
        const long i = t * 8;
        float4 a = *(const float4*)(x + i);
        float4 b = *(const float4*)(x + i + 4);
        float v[8] = {a.x, a.y, a.z, a.w, b.x, b.y, b.z, b.w};
        __half2 hh[4], ll[4];
#pragma unroll
        for (int j = 0; j < 4; j++) {
            f16 h0 = __float2half_rn(v[2*j]);
            f16 h1 = __float2half_rn(v[2*j+1]);
            hh[j] = __halves2half2(h0, h1);
            ll[j] = __halves2half2(__float2half_rn(v[2*j]   - __half2float(h0)),
                                   __float2half_rn(v[2*j+1] - __half2float(h1)));
        }
        *(uint4*)(xh + i) = *(uint4*)hh;
        *(uint4*)(xl + i) = *(uint4*)ll;
        return;
    }
    t -= R0;
    if (t < (long)R1) { conv8(wq + t * 8, wc + t * 8); return; }
    t -= R1;
    if (t < (long)R2) { conv8(wk + t * 8, wc + (size_t)KOFF * DIM + t * 8); return; }
    t -= R2;
    if (t < (long)R3) { conv8(wv + t * 8, wc + (size_t)VOFF * DIM + t * 8); return; }
    t -= R3;
    if (t < (long)R4) { conv8(wo + t * 8, wo16 + t * 8); return; }
    t -= R4;
    if (t < (long)R5) {
        const int i = (int)t * 8;
#pragma unroll
        for (int j = 0; j < 8; j++) {
            const int c = i + j;
            bqkv[c] = (c < KOFF) ? qb[c] : (c < VOFF ? kb[c - KOFF] : vb[c - VOFF]);
        }
    }
}

// ---------------------------------------------------------------------------
// fp16x2 mma.sync GEMM (NT): C = Ah*B^T + Al*B^T + bias
// Block 128x128, BK=32, 3-stage cp.async ring, XOR-swizzled 64B rows,
// 256 thr = 8 warps (4m x 2n), warp tile 32x64. 2 CTAs/SM (144KB smem).
// ---------------------------------------------------------------------------
#define TILEB 8192u                 // one operand tile: 128 rows x 64 bytes
#define STAGEB (3u*TILEB)           // Ah, Al, B = 24 KB
#define NSTG 3
#define GSMEM_BYTES (NSTG*STAGEB)   // 72 KB

__device__ __forceinline__ void cpa16(unsigned dst, const void* src) {
    asm volatile("cp.async.cg.shared.global [%0], [%1], 16;" :: "r"(dst), "l"(src));
}
__device__ __forceinline__ void cpa16p(unsigned dst, const void* src, int sz) {
    asm volatile("cp.async.cg.shared.global [%0], [%1], 16, %2;"
                 :: "r"(dst), "l"(src), "r"(sz));
}

__global__ __launch_bounds__(256, 2) void gemm_f16x2(
    const f16* __restrict__ Ah, const f16* __restrict__ Al,
    const f16* __restrict__ B,
    const float* __restrict__ bias, float* __restrict__ C,
    int M, int N, int K)
{
    extern __shared__ char dsm[];
    unsigned sb;
    { unsigned long long t = __cvta_generic_to_shared(dsm); sb = (unsigned)t; }

    const int tid  = threadIdx.x;
    const int wid  = tid >> 5;
    const int lane = tid & 31;
    const int bm   = blockIdx.y * 128;
    const int bn   = blockIdx.x * 128;
    const int wm   = (wid & 3) * 32;
    const int wn   = (wid >> 2) * 64;
    const int g    = lane >> 2;
    const int tg   = lane & 3;

    const int KT = K / 32;

    const int r0c = tid >> 2;            // rows 0..63 (chunk 0), +64 (chunk 1)
    const int c0c = tid & 3;             // 16B segment 0..3

#define SWOFF(r, c) ((unsigned)((r) * 64 + ((((c) ^ (((r) >> 1) & 3))) << 4)))

#define ISSUE_STAGE(sidx, k0)                                                  \
    do {                                                                       \
        const unsigned tb = sb + (unsigned)(sidx) * STAGEB;                    \
        _Pragma("unroll")                                                      \
        for (int it = 0; it < 2; it++) {                                       \
            const int r = r0c + it * 64;                                       \
            const unsigned so = SWOFF(r, c0c);                                 \
            const size_t ao = (size_t)(bm + r) * K + (k0) + c0c * 8;           \
            const int brw = bn + r;                                            \
            const int pz  = (brw < N) ? 16 : 0;                                \
            const size_t bo = (size_t)((brw < N) ? brw : 0) * K + (k0) + c0c * 8; \
            cpa16 (tb + so,             Ah + ao);                              \
            cpa16 (tb + TILEB + so,     Al + ao);                              \
            cpa16p(tb + 2 * TILEB + so, B + bo, pz);                           \
        }                                                                      \
        asm volatile("cp.async.commit_group;");                                \
    } while (0)

    float acc[2][8][4];
#pragma unroll
    for (int mi = 0; mi < 2; mi++)
#pragma unroll
        for (int ni = 0; ni < 8; ni++)
#pragma unroll
            for (int r = 0; r < 4; r++) acc[mi][ni][r] = 0.f;

    ISSUE_STAGE(0, 0);
    ISSUE_STAGE(1, 32);

    const int a_row = ((lane >> 3) & 1) * 8 + (lane & 7);
    const int a_ch  = (lane >> 4) & 1;
    const int b_row = ((lane >> 4) & 1) * 8 + (lane & 7);
    const int b_ch  = (lane >> 3) & 1;

    for (int kt = 0; kt < KT; kt++) {
        asm volatile("cp.async.wait_group %0;" :: "n"(1));
        __syncthreads();

        if (kt + 2 < KT) ISSUE_STAGE((kt + 2) % NSTG, (kt + 2) * 32);
        else             asm volatile("cp.async.commit_group;");

        const unsigned stb = sb + (unsigned)(kt % NSTG) * STAGEB;

#pragma unroll
        for (int ks = 0; ks < 2; ks++) {
            unsigned fAh[2][4], fAl[2][4], fB[8][2];
            const int ca = ks * 2 + a_ch;
            const int cb = ks * 2 + b_ch;

#pragma unroll
            for (int mi = 0; mi < 2; mi++) {
                const int r = wm + mi * 16 + a_row;
                const unsigned ad = stb + SWOFF(r, ca);
                asm volatile("ldmatrix.sync.aligned.m8n8.x4.shared.b16 {%0,%1,%2,%3}, [%4];"
                    : "=r"(fAh[mi][0]), "=r"(fAh[mi][1]), "=r"(fAh[mi][2]), "=r"(fAh[mi][3])
                    : "r"(ad));
                asm volatile("ldmatrix.sync.aligned.m8n8.x4.shared.b16 {%0,%1,%2,%3}, [%4];"
                    : "=r"(fAl[mi][0]), "=r"(fAl[mi][1]), "=r"(fAl[mi][2]), "=r"(fAl[mi][3])
                    : "r"(ad + TILEB));
            }
#pragma unroll
            for (int p = 0; p < 4; p++) {
                const int r = wn + p * 16 + b_row;
                const unsigned bd = stb + 2u * TILEB + SWOFF(r, cb);
                asm volatile("ldmatrix.sync.aligned.m8n8.x4.shared.b16 {%0,%1,%2,%3}, [%4];"
                    : "=r"(fB[2*p][0]), "=r"(fB[2*p][1]), "=r"(fB[2*p+1][0]), "=r"(fB[2*p+1][1])
                    : "r"(bd));
            }

#define MMA(d, a, b)                                                           \
    asm volatile("mma.sync.aligned.m16n8k16.row.col.f32.f16.f16.f32 "          \
                 "{%0,%1,%2,%3}, {%4,%5,%6,%7}, {%8,%9}, {%0,%1,%2,%3};"       \
                 : "+f"((d)[0]), "+f"((d)[1]), "+f"((d)[2]), "+f"((d)[3])      \
                 : "r"((a)[0]), "r"((a)[1]), "r"((a)[2]), "r"((a)[3]),         \
                   "r"((b)[0]), "r"((b)[1]))

#pragma unroll
            for (int ni = 0; ni < 8; ni++)
#pragma unroll
                for (int mi = 0; mi < 2; mi++)
                    MMA(acc[mi][ni], fAh[mi], fB[ni]);
#pragma unroll
            for (int ni = 0; ni < 8; ni++)
#pragma unroll
                for (int mi = 0; mi < 2; mi++)
                    MMA(acc[mi][ni], fAl[mi], fB[ni]);
#undef MMA
        }
    }

    // epilogue
#pragma unroll
    for (int mi = 0; mi < 2; mi++) {
        const int row = bm + wm + mi * 16 + g;
#pragma unroll
        for (int ni = 0; ni < 8; ni++) {
            const int col = bn + wn + ni * 8 + tg * 2;
            if (col < N) {
                const float bx = bias[col], by = bias[col + 1];
                float2 v0 = make_float2(acc[mi][ni][0] + bx, acc[mi][ni][1] + by);
                float2 v1 = make_float2(acc[mi][ni][2] + bx, acc[mi][ni][3] + by);
                *(float2*)(C + (size_t)row * N + col)       = v0;
                *(float2*)(C + (size_t)(row + 8) * N + col) = v1;
            }
        }
    }
#undef ISSUE_STAGE
#undef SWOFF
}

// ---------------------------------------------------------------------------
// RoPE, in-place on rows of stride `rstride`, heads at column `coff`.
// ---------------------------------------------------------------------------
__global__ void rope_kernel(float* __restrict__ t, const float* __restrict__ rope,
                            int n_heads, int rstride, int coff)
{
    const int idx = blockIdx.x * blockDim.x + threadIdx.x;
    const int total = SEQ * n_heads * 32;
    if (idx >= total) return;
    const int d = idx & 31;
    const int h = (idx >> 5) % n_heads;
    const int s = idx / (32 * n_heads);

    const float c1 = rope[s * 128 + d];
    const float c2 = rope[s * 128 + d + 32];
    const float s1 = rope[s * 128 + 64 + d];
    const float s2 = rope[s * 128 + 96 + d];

    float* base = t + (size_t)s * rstride + coff + h * HD;
    const float x1 = base[d];
    const float x2 = base[d + 32];
    base[d]      = x1 * c1 - x2 * s1;
    base[d + 32] = x2 * c2 + x1 * s2;
}

// ---------------------------------------------------------------------------
// Sliding-window attention + sink gating. One warp per (query, head).
// Writes fp16 hi/lo split of the output directly (feeds O-proj GEMM).
// ---------------------------------------------------------------------------
__global__ __launch_bounds__(128) void attn_kernel(
    const float* __restrict__ qkv, const float* __restrict__ sinks,
    f16* __restrict__ oh, f16* __restrict__ ol)
{
    const float scale = 0.16832169945461f;  // (0.1*ln(32)+1)/8
    const int w    = threadIdx.x >> 5;
    const int lane = threadIdx.x & 31;
    const int p = blockIdx.x * 4 + w;
    const int i = p & (SEQ - 1);
    const int h = p >> 11;

    __shared__ float shq[4][64];
    __shared__ float shp[4][128];

    const float* qrow = qkv + (size_t)i * QKVN + h * HD;
    shq[w][lane]      = qrow[lane];
    shq[w][lane + 32] = qrow[lane + 32];
    __syncwarp();

    const int kvh = h >> 3;
    int start = i - (WINDOW - 1); if (start < 0) start = 0;
    const int cnt = i - start + 1;

    float sc[4];
#pragma unroll
    for (int t = 0; t < 4; t++) {
        const int jj = lane + 32 * t;
        if (jj < cnt) {
            const float4* krow =
                (const float4*)(qkv + (size_t)(start + jj) * QKVN + KOFF + kvh * HD);
            float s = 0.f;
#pragma unroll
            for (int d4 = 0; d4 < 16; d4++) {
                const float4 kk = krow[d4];
                s = fmaf(kk.x, shq[w][d4 * 4 + 0], s);
                s = fmaf(kk.y, shq[w][d4 * 4 + 1], s);
                s = fmaf(kk.z, shq[w][d4 * 4 + 2], s);
                s = fmaf(kk.w, shq[w][d4 * 4 + 3], s);
            }
            sc[t] = s * scale;
        } else {
            sc[t] = -1e30f;
        }
    }

    float m = fmaxf(fmaxf(sc[0], sc[1]), fmaxf(sc[2], sc[3]));
#pragma unroll
    for (int o = 16; o; o >>= 1) m = fmaxf(m, __shfl_xor_sync(0xffffffffu, m, o));

    float e[4], sum = 0.f;
#pragma unroll
    for (int t = 0; t < 4; t++) { e[t] = expf(sc[t] - m); sum += e[t]; }
#pragma unroll
    for (int o = 16; o; o >>= 1) sum += __shfl_xor_sync(0xffffffffu, sum, o);

    const float lse  = m + logf(sum);
    const float sig  = 1.f / (1.f + expf(sinks[h] - lse));
    const float wsc  = sig / sum;
#pragma unroll
    for (int t = 0; t < 4; t++) shp[w][lane + 32 * t] = e[t] * wsc;
    __syncwarp();

    float acc0 = 0.f, acc1 = 0.f;
    for (int jj = 0; jj < cnt; jj++) {
        const float pj = shp[w][jj];
        const float* vrow = qkv + (size_t)(start + jj) * QKVN + VOFF + kvh * HD;
        acc0 = fmaf(pj, vrow[lane], acc0);
        acc1 = fmaf(pj, vrow[lane + 32], acc1);
    }

    const size_t ob = (size_t)i * QDIM + h * HD;
    f16 h0 = __float2half_rn(acc0);
    f16 h1 = __float2half_rn(acc1);
    oh[ob + lane]      = h0;
    oh[ob + lane + 32] = h1;
    ol[ob + lane]      = __float2half_rn(acc0 - __half2float(h0));
    ol[ob + lane + 32] = __float2half_rn(acc1 - __half2float(h1));
}

// ---------------------------------------------------------------------------
extern "C" void kernel_launch(void* const* d_in, const int* in_sizes, int n_in,
                              void* d_out, int out_size)
{
    const float* x     = (const float*)d_in[0];
    const float* rope  = (const float*)d_in[1];
    const float* wq_w  = (const float*)d_in[2];
    const float* wq_b  = (const float*)d_in[3];
    const float* wk_w  = (const float*)d_in[4];
    const float* wk_b  = (const float*)d_in[5];
    const float* wv_w  = (const float*)d_in[6];
    const float* wv_b  = (const float*)d_in[7];
    const float* wo_w  = (const float*)d_in[8];
    const float* wo_b  = (const float*)d_in[9];
    const float* sinks = (const float*)d_in[10];
    float* out = (float*)d_out;

    float *qkv, *bqkv;
    cudaGetSymbolAddress((void**)&qkv,  g_qkv);
    cudaGetSymbolAddress((void**)&bqkv, g_bqkv);

    f16 *xh, *xl, *wc, *wo, *ah, *al;
    cudaGetSymbolAddress((void**)&xh, g_xh); cudaGetSymbolAddress((void**)&xl, g_xl);
    cudaGetSymbolAddress((void**)&wc, g_wc); cudaGetSymbolAddress((void**)&wo, g_wo);
    cudaGetSymbolAddress((void**)&ah, g_ah); cudaGetSymbolAddress((void**)&al, g_al);

    cudaFuncSetAttribute(gemm_f16x2, cudaFuncAttributeMaxDynamicSharedMemorySize,
                         GSMEM_BYTES);

    // fused prep: all converts/splits/concat in one launch
    prep<<<(unsigned)((PREP_THREADS + 255) / 256), 256>>>(
        x, wq_w, wk_w, wv_w, wo_w, wq_b, wk_b, wv_b,
        xh, xl, wc, wo, bqkv);

    // fused QKV projection: [2048 x 5120], 640 CTAs
    gemm_f16x2<<<dim3(QKVN / 128, SEQ / 128), 256, GSMEM_BYTES>>>(
        xh, xl, wc, bqkv, qkv, SEQ, QKVN, DIM);

    // RoPE on q (64 heads at col 0) and k (8 heads at col 4096)
    rope_kernel<<<(SEQ * NH * 32 + 255) / 256, 256>>>(qkv, rope, NH, QKVN, 0);
    rope_kernel<<<(SEQ * NKV * 32 + 255) / 256, 256>>>(qkv, rope, NKV, QKVN, KOFF);

    // attention (writes fp16 hi/lo split directly)
    attn_kernel<<<SEQ * NH / 4, 128>>>(qkv, sinks, ah, al);

    // O-projection
    gemm_f16x2<<<dim3((DIM + 127) / 128, SEQ / 128), 256, GSMEM_BYTES>>>(
        ah, al, wo, wo_b, out, SEQ, DIM, QDIM);
}

// round 10
// speedup vs baseline: 1.5922x; 1.1859x over previous
#include <cuda_runtime.h>
#include <cuda_fp16.h>
#include <math.h>

#define SEQ 2048
#define DIM 2880
#define NH 64
#define NKV 8
#define HD 64
#define QDIM (NH*HD)     // 4096
#define KVDIM (NKV*HD)   // 512
#define QKVN 5120        // 4096 + 512 + 512
#define KOFF 4096
#define VOFF 4608
#define WINDOW 128

typedef __half f16;

// fp32 scratch
__device__ float g_qkv[SEQ * QKVN];    // 40 MB: q | k | v per row
__device__ float g_bqkv[QKVN];

// fp16 operand scratch
__device__ f16 g_x16[SEQ * DIM];       // x (fp16)
__device__ f16 g_wc[QKVN * DIM];       // concat wq|wk|wv (fp16)
__device__ f16 g_wo[DIM * QDIM];       // wo (fp16)
__device__ f16 g_a16[SEQ * QDIM];      // attn out (fp16)

// ---------------------------------------------------------------------------
// Fused prep: x -> fp16, wq/wk/wv -> wc fp16, wo -> fp16, bias concat.
// ---------------------------------------------------------------------------
#define R0 (SEQ*DIM/8)          // x
#define R1 (QDIM*DIM/8)         // wq
#define R2 (KVDIM*DIM/8)        // wk
#define R3 (KVDIM*DIM/8)        // wv
#define R4 ((size_t)DIM*QDIM/8) // wo
#define R5 (QKVN/8)             // bias concat
#define PREP_THREADS (R0+R1+R2+R3+R4+R5)

__device__ __forceinline__ void conv8(const float* __restrict__ s, f16* __restrict__ d) {
    float4 a = *(const float4*)s;
    float4 b = *(const float4*)(s + 4);
    __half2 hh[4];
    hh[0] = __halves2half2(__float2half_rn(a.x), __float2half_rn(a.y));
    hh[1] = __halves2half2(__float2half_rn(a.z), __float2half_rn(a.w));
    hh[2] = __halves2half2(__float2half_rn(b.x), __float2half_rn(b.y));
    hh[3] = __halves2half2(__float2half_rn(b.z), __float2half_rn(b.w));
    *(uint4*)d = *(uint4*)hh;
}

__global__ void prep(const float* __restrict__ x,
                     const float* __restrict__ wq, const float* __restrict__ wk,
                     const float* __restrict__ wv, const float* __restrict__ wo,
                     const float* __restrict__ qb, const float* __restrict__ kb,
                     const float* __restrict__ vb,
                     f16* __restrict__ x16,
                     f16* __restrict__ wc, f16* __restrict__ wo16,
                     float* __restrict__ bqkv)
{
    long t = (long)blockIdx.x * blockDim.x + threadIdx.x;
    if (t < (long)R0) { conv8(x + t * 8, x16 + t * 8); return; }
    t -= R0;
    if (t < (long)R1) { conv8(wq + t * 8, wc + t * 8); return; }
    t -= R1;
    if (t < (long)R2) { conv8(wk + t * 8, wc + (size_t)KOFF * DIM + t * 8); return; }
    t -= R2;
    if (t < (long)R3) { conv8(wv + t * 8, wc + (size_t)VOFF * DIM + t * 8); return; }
    t -= R3;
    if (t < (long)R4) { conv8(wo + t * 8, wo16 + t * 8); return; }
    t -= R4;
    if (t < (long)R5) {
        const int i = (int)t * 8;
#pragma unroll
        for (int j = 0; j < 8; j++) {
            const int c = i + j;
            bqkv[c] = (c < KOFF) ? qb[c] : (c < VOFF ? kb[c - KOFF] : vb[c - VOFF]);
        }
    }
}

// ---------------------------------------------------------------------------
// fp16 mma.sync GEMM (NT): C = A*B^T + bias
// Block 128x128, BK=32, 3-stage cp.async ring, XOR-swizzled 64B rows,
// 256 thr = 8 warps (4m x 2n), warp tile 32x64. 2 CTAs/SM.
// ---------------------------------------------------------------------------
#define TILEB 8192u                 // one operand tile: 128 rows x 64 bytes
#define STAGEB (2u*TILEB)           // A, B = 16 KB
#define NSTG 3
#define GSMEM_BYTES (NSTG*STAGEB)   // 48 KB

__device__ __forceinline__ void cpa16(unsigned dst, const void* src) {
    asm volatile("cp.async.cg.shared.global [%0], [%1], 16;" :: "r"(dst), "l"(src));
}
__device__ __forceinline__ void cpa16p(unsigned dst, const void* src, int sz) {
    asm volatile("cp.async.cg.shared.global [%0], [%1], 16, %2;"
                 :: "r"(dst), "l"(src), "r"(sz));
}

__global__ __launch_bounds__(256, 2) void gemm_f16(
    const f16* __restrict__ A, const f16* __restrict__ B,
    const float* __restrict__ bias, float* __restrict__ C,
    int M, int N, int K)
{
    extern __shared__ char dsm[];
    unsigned sb;
    { unsigned long long t = __cvta_generic_to_shared(dsm); sb = (unsigned)t; }

    const int tid  = threadIdx.x;
    const int wid  = tid >> 5;
    const int lane = tid & 31;
    const int bm   = blockIdx.y * 128;
    const int bn   = blockIdx.x * 128;
    const int wm   = (wid & 3) * 32;
    const int wn   = (wid >> 2) * 64;
    const int g    = lane >> 2;
    const int tg   = lane & 3;

    const int KT = K / 32;

    const int r0c = tid >> 2;            // rows 0..63 (chunk 0), +64 (chunk 1)
    const int c0c = tid & 3;             // 16B segment 0..3

#define SWOFF(r, c) ((unsigned)((r) * 64 + ((((c) ^ (((r) >> 1) & 3))) << 4)))

#define ISSUE_STAGE(sidx, k0)                                                  \
    do {                                                                       \
        const unsigned tb = sb + (unsigned)(sidx) * STAGEB;                    \
        _Pragma("unroll")                                                      \
        for (int it = 0; it < 2; it++) {                                       \
            const int r = r0c + it * 64;                                       \
            const unsigned so = SWOFF(r, c0c);                                 \
            const size_t ao = (size_t)(bm + r) * K + (k0) + c0c * 8;           \
            const int brw = bn + r;                                            \
            const int pz  = (brw < N) ? 16 : 0;                                \
            const size_t bo = (size_t)((brw < N) ? brw : 0) * K + (k0) + c0c * 8; \
            cpa16 (tb + so,         A + ao);                                   \
            cpa16p(tb + TILEB + so, B + bo, pz);                               \
        }                                                                      \
        asm volatile("cp.async.commit_group;");                                \
    } while (0)

    float acc[2][8][4];
#pragma unroll
    for (int mi = 0; mi < 2; mi++)
#pragma unroll
        for (int ni = 0; ni < 8; ni++)
#pragma unroll
            for (int r = 0; r < 4; r++) acc[mi][ni][r] = 0.f;

    ISSUE_STAGE(0, 0);
    ISSUE_STAGE(1, 32);

    const int a_row = ((lane >> 3) & 1) * 8 + (lane & 7);
    const int a_ch  = (lane >> 4) & 1;
    const int b_row = ((lane >> 4) & 1) * 8 + (lane & 7);
    const int b_ch  = (lane >> 3) & 1;

    for (int kt = 0; kt < KT; kt++) {
        asm volatile("cp.async.wait_group %0;" :: "n"(1));
        __syncthreads();

        if (kt + 2 < KT) ISSUE_STAGE((kt + 2) % NSTG, (kt + 2) * 32);
        else             asm volatile("cp.async.commit_group;");

        const unsigned stb = sb + (unsigned)(kt % NSTG) * STAGEB;

#pragma unroll
        for (int ks = 0; ks < 2; ks++) {
            unsigned fA[2][4], fB[8][2];
            const int ca = ks * 2 + a_ch;
            const int cb = ks * 2 + b_ch;

#pragma unroll
            for (int mi = 0; mi < 2; mi++) {
                const int r = wm + mi * 16 + a_row;
                const unsigned ad = stb + SWOFF(r, ca);
                asm volatile("ldmatrix.sync.aligned.m8n8.x4.shared.b16 {%0,%1,%2,%3}, [%4];"
                    : "=r"(fA[mi][0]), "=r"(fA[mi][1]), "=r"(fA[mi][2]), "=r"(fA[mi][3])
                    : "r"(ad));
            }
#pragma unroll
            for (int p = 0; p < 4; p++) {
                const int r = wn + p * 16 + b_row;
                const unsigned bd = stb + TILEB + SWOFF(r, cb);
                asm volatile("ldmatrix.sync.aligned.m8n8.x4.shared.b16 {%0,%1,%2,%3}, [%4];"
                    : "=r"(fB[2*p][0]), "=r"(fB[2*p][1]), "=r"(fB[2*p+1][0]), "=r"(fB[2*p+1][1])
                    : "r"(bd));
            }

#define MMA(d, a, b)                                                           \
    asm volatile("mma.sync.aligned.m16n8k16.row.col.f32.f16.f16.f32 "          \
                 "{%0,%1,%2,%3}, {%4,%5,%6,%7}, {%8,%9}, {%0,%1,%2,%3};"       \
                 : "+f"((d)[0]), "+f"((d)[1]), "+f"((d)[2]), "+f"((d)[3])      \
                 : "r"((a)[0]), "r"((a)[1]), "r"((a)[2]), "r"((a)[3]),         \
                   "r"((b)[0]), "r"((b)[1]))

#pragma unroll
            for (int ni = 0; ni < 8; ni++)
#pragma unroll
                for (int mi = 0; mi < 2; mi++)
                    MMA(acc[mi][ni], fA[mi], fB[ni]);
#undef MMA
        }
    }

    // epilogue
#pragma unroll
    for (int mi = 0; mi < 2; mi++) {
        const int row = bm + wm + mi * 16 + g;
#pragma unroll
        for (int ni = 0; ni < 8; ni++) {
            const int col = bn + wn + ni * 8 + tg * 2;
            if (col < N) {
                const float bx = bias[col], by = bias[col + 1];
                float2 v0 = make_float2(acc[mi][ni][0] + bx, acc[mi][ni][1] + by);
                float2 v1 = make_float2(acc[mi][ni][2] + bx, acc[mi][ni][3] + by);
                *(float2*)(C + (size_t)row * N + col)       = v0;
                *(float2*)(C + (size_t)(row + 8) * N + col) = v1;
            }
        }
    }
#undef ISSUE_STAGE
#undef SWOFF
}

// ---------------------------------------------------------------------------
// RoPE, in-place on rows of stride `rstride`, heads at column `coff`.
// ---------------------------------------------------------------------------
__global__ void rope_kernel(float* __restrict__ t, const float* __restrict__ rope,
                            int n_heads, int rstride, int coff)
{
    const int idx = blockIdx.x * blockDim.x + threadIdx.x;
    const int total = SEQ * n_heads * 32;
    if (idx >= total) return;
    const int d = idx & 31;
    const int h = (idx >> 5) % n_heads;
    const int s = idx / (32 * n_heads);

    const float c1 = rope[s * 128 + d];
    const float c2 = rope[s * 128 + d + 32];
    const float s1 = rope[s * 128 + 64 + d];
    const float s2 = rope[s * 128 + 96 + d];

    float* base = t + (size_t)s * rstride + coff + h * HD;
    const float x1 = base[d];
    const float x2 = base[d + 32];
    base[d]      = x1 * c1 - x2 * s1;
    base[d + 32] = x2 * c2 + x1 * s2;
}

// ---------------------------------------------------------------------------
// Sliding-window attention + sink gating. One warp per (query, head).
// Writes fp16 output directly (feeds O-proj GEMM).
// ---------------------------------------------------------------------------
__global__ __launch_bounds__(128) void attn_kernel(
    const float* __restrict__ qkv, const float* __restrict__ sinks,
    f16* __restrict__ o16)
{
    const float scale = 0.16832169945461f;  // (0.1*ln(32)+1)/8
    const int w    = threadIdx.x >> 5;
    const int lane = threadIdx.x & 31;
    const int p = blockIdx.x * 4 + w;
    const int i = p & (SEQ - 1);
    const int h = p >> 11;

    __shared__ float shq[4][64];
    __shared__ float shp[4][128];

    const float* qrow = qkv + (size_t)i * QKVN + h * HD;
    shq[w][lane]      = qrow[lane];
    shq[w][lane + 32] = qrow[lane + 32];
    __syncwarp();

    const int kvh = h >> 3;
    int start = i - (WINDOW - 1); if (start < 0) start = 0;
    const int cnt = i - start + 1;

    float sc[4];
#pragma unroll
    for (int t = 0; t < 4; t++) {
        const int jj = lane + 32 * t;
        if (jj < cnt) {
            const float4* krow =
                (const float4*)(qkv + (size_t)(start + jj) * QKVN + KOFF + kvh * HD);
            float s = 0.f;
#pragma unroll
            for (int d4 = 0; d4 < 16; d4++) {
                const float4 kk = krow[d4];
                s = fmaf(kk.x, shq[w][d4 * 4 + 0], s);
                s = fmaf(kk.y, shq[w][d4 * 4 + 1], s);
                s = fmaf(kk.z, shq[w][d4 * 4 + 2], s);
                s = fmaf(kk.w, shq[w][d4 * 4 + 3], s);
            }
            sc[t] = s * scale;
        } else {
            sc[t] = -1e30f;
        }
    }

    float m = fmaxf(fmaxf(sc[0], sc[1]), fmaxf(sc[2], sc[3]));
#pragma unroll
    for (int o = 16; o; o >>= 1) m = fmaxf(m, __shfl_xor_sync(0xffffffffu, m, o));

    float e[4], sum = 0.f;
#pragma unroll
    for (int t = 0; t < 4; t++) { e[t] = expf(sc[t] - m); sum += e[t]; }
#pragma unroll
    for (int o = 16; o; o >>= 1) sum += __shfl_xor_sync(0xffffffffu, sum, o);

    const float lse  = m + logf(sum);
    const float sig  = 1.f / (1.f + expf(sinks[h] - lse));
    const float wsc  = sig / sum;
#pragma unroll
    for (int t = 0; t < 4; t++) shp[w][lane + 32 * t] = e[t] * wsc;
    __syncwarp();

    float acc0 = 0.f, acc1 = 0.f;
    for (int jj = 0; jj < cnt; jj++) {
        const float pj = shp[w][jj];
        const float* vrow = qkv + (size_t)(start + jj) * QKVN + VOFF + kvh * HD;
        acc0 = fmaf(pj, vrow[lane], acc0);
        acc1 = fmaf(pj, vrow[lane + 32], acc1);
    }

    const size_t ob = (size_t)i * QDIM + h * HD;
    o16[ob + lane]      = __float2half_rn(acc0);
    o16[ob + lane + 32] = __float2half_rn(acc1);
}

// ---------------------------------------------------------------------------
extern "C" void kernel_launch(void* const* d_in, const int* in_sizes, int n_in,
                              void* d_out, int out_size)
{
    const float* x     = (const float*)d_in[0];
    const float* rope  = (const float*)d_in[1];
    const float* wq_w  = (const float*)d_in[2];
    const float* wq_b  = (const float*)d_in[3];
    const float* wk_w  = (const float*)d_in[4];
    const float* wk_b  = (const float*)d_in[5];
    const float* wv_w  = (const float*)d_in[6];
    const float* wv_b  = (const float*)d_in[7];
    const float* wo_w  = (const float*)d_in[8];
    const float* wo_b  = (const float*)d_in[9];
    const float* sinks = (const float*)d_in[10];
    float* out = (float*)d_out;

    float *qkv, *bqkv;
    cudaGetSymbolAddress((void**)&qkv,  g_qkv);
    cudaGetSymbolAddress((void**)&bqkv, g_bqkv);

    f16 *x16, *wc, *wo, *a16;
    cudaGetSymbolAddress((void**)&x16, g_x16);
    cudaGetSymbolAddress((void**)&wc, g_wc); cudaGetSymbolAddress((void**)&wo, g_wo);
    cudaGetSymbolAddress((void**)&a16, g_a16);

    cudaFuncSetAttribute(gemm_f16, cudaFuncAttributeMaxDynamicSharedMemorySize,
                         GSMEM_BYTES);

    // fused prep: all converts/concat in one launch
    prep<<<(unsigned)((PREP_THREADS + 255) / 256), 256>>>(
        x, wq_w, wk_w, wv_w, wo_w, wq_b, wk_b, wv_b,
        x16, wc, wo, bqkv);

    // fused QKV projection: [2048 x 5120], 640 CTAs
    gemm_f16<<<dim3(QKVN / 128, SEQ / 128), 256, GSMEM_BYTES>>>(
        x16, wc, bqkv, qkv, SEQ, QKVN, DIM);

    // RoPE on q (64 heads at col 0) and k (8 heads at col 4096)
    rope_kernel<<<(SEQ * NH * 32 + 255) / 256, 256>>>(qkv, rope, NH, QKVN, 0);
    rope_kernel<<<(SEQ * NKV * 32 + 255) / 256, 256>>>(qkv, rope, NKV, QKVN, KOFF);

    // attention (writes fp16 directly)
    attn_kernel<<<SEQ * NH / 4, 128>>>(qkv, sinks, a16);

    // O-projection
    gemm_f16<<<dim3((DIM + 127) / 128, SEQ / 128), 256, GSMEM_BYTES>>>(
        a16, wo, wo_b, out, SEQ, DIM, QDIM);
}

// round 11
// speedup vs baseline: 3.0719x; 1.9293x over previous
#include <cuda_runtime.h>
#include <cuda_fp16.h>
#include <math.h>

#define SEQ 2048
#define DIM 2880
#define NH 64
#define NKV 8
#define HD 64
#define QDIM (NH*HD)     // 4096
#define KVDIM (NKV*HD)   // 512
#define QKVN 5120        // 4096 + 512 + 512
#define KOFF 4096
#define VOFF 4608
#define WINDOW 128

typedef __half f16;

// fp32 scratch
__device__ float g_qkv[SEQ * QKVN];    // 40 MB: q | k | v per row
__device__ float g_bqkv[QKVN];

// fp16 operand scratch
__device__ f16 g_x16[SEQ * DIM];       // x (fp16)
__device__ f16 g_wc[QKVN * DIM];       // concat wq|wk|wv (fp16)
__device__ f16 g_wo[DIM * QDIM];       // wo (fp16)
__device__ f16 g_a16[SEQ * QDIM];      // attn out (fp16)

// ---------------------------------------------------------------------------
// Fused prep: x -> fp16, wq/wk/wv -> wc fp16, wo -> fp16, bias concat.
// ---------------------------------------------------------------------------
#define R0 (SEQ*DIM/8)
#define R1 (QDIM*DIM/8)
#define R2 (KVDIM*DIM/8)
#define R3 (KVDIM*DIM/8)
#define R4 ((size_t)DIM*QDIM/8)
#define R5 (QKVN/8)
#define PREP_THREADS (R0+R1+R2+R3+R4+R5)

__device__ __forceinline__ void conv8(const float* __restrict__ s, f16* __restrict__ d) {
    float4 a = *(const float4*)s;
    float4 b = *(const float4*)(s + 4);
    __half2 hh[4];
    hh[0] = __halves2half2(__float2half_rn(a.x), __float2half_rn(a.y));
    hh[1] = __halves2half2(__float2half_rn(a.z), __float2half_rn(a.w));
    hh[2] = __halves2half2(__float2half_rn(b.x), __float2half_rn(b.y));
    hh[3] = __halves2half2(__float2half_rn(b.z), __float2half_rn(b.w));
    *(uint4*)d = *(uint4*)hh;
}

__global__ void prep(const float* __restrict__ x,
                     const float* __restrict__ wq, const float* __restrict__ wk,
                     const float* __restrict__ wv, const float* __restrict__ wo,
                     const float* __restrict__ qb, const float* __restrict__ kb,
                     const float* __restrict__ vb,
                     f16* __restrict__ x16,
                     f16* __restrict__ wc, f16* __restrict__ wo16,
                     float* __restrict__ bqkv)
{
    long t = (long)blockIdx.x * blockDim.x + threadIdx.x;
    if (t < (long)R0) { conv8(x + t * 8, x16 + t * 8); return; }
    t -= R0;
    if (t < (long)R1) { conv8(wq + t * 8, wc + t * 8); return; }
    t -= R1;
    if (t < (long)R2) { conv8(wk + t * 8, wc + (size_t)KOFF * DIM + t * 8); return; }
    t -= R2;
    if (t < (long)R3) { conv8(wv + t * 8, wc + (size_t)VOFF * DIM + t * 8); return; }
    t -= R3;
    if (t < (long)R4) { conv8(wo + t * 8, wo16 + t * 8); return; }
    t -= R4;
    if (t < (long)R5) {
        const int i = (int)t * 8;
#pragma unroll
        for (int j = 0; j < 8; j++) {
            const int c = i + j;
            bqkv[c] = (c < KOFF) ? qb[c] : (c < VOFF ? kb[c - KOFF] : vb[c - VOFF]);
        }
    }
}

// ---------------------------------------------------------------------------
// fp16 mma.sync GEMM (NT): C = A*B^T + bias
// Block 128x128, BK=64, 3-stage cp.async ring, SW128-swizzled 128B rows,
// 256 thr = 8 warps (4m x 2n), warp tile 32x64. 2 CTAs/SM (192KB smem).
// ---------------------------------------------------------------------------
#define TILEB 16384u                // one operand tile: 128 rows x 128 bytes
#define STAGEB (2u*TILEB)           // A, B = 32 KB
#define NSTG 3
#define GSMEM_BYTES (NSTG*STAGEB)   // 96 KB

__device__ __forceinline__ void cpa16(unsigned dst, const void* src) {
    asm volatile("cp.async.cg.shared.global [%0], [%1], 16;" :: "r"(dst), "l"(src));
}
__device__ __forceinline__ void cpa16p(unsigned dst, const void* src, int sz) {
    asm volatile("cp.async.cg.shared.global [%0], [%1], 16, %2;"
                 :: "r"(dst), "l"(src), "r"(sz));
}

__global__ __launch_bounds__(256, 2) void gemm_f16(
    const f16* __restrict__ A, const f16* __restrict__ B,
    const float* __restrict__ bias, float* __restrict__ C,
    int M, int N, int K)
{
    extern __shared__ char dsm[];
    unsigned sb;
    { unsigned long long t = __cvta_generic_to_shared(dsm); sb = (unsigned)t; }

    const int tid  = threadIdx.x;
    const int wid  = tid >> 5;
    const int lane = tid & 31;
    const int bm   = blockIdx.y * 128;
    const int bn   = blockIdx.x * 128;
    const int wm   = (wid & 3) * 32;
    const int wn   = (wid >> 2) * 64;
    const int g    = lane >> 2;
    const int tg   = lane & 3;

    const int KT = K / 64;

    // cp.async mapping: 1024 x 16B per tile, 4 per thread
    const int r0c = tid >> 3;            // base row 0..31 (stride 32 over it)
    const int c0c = tid & 7;             // 16B segment 0..7

#define SWOFF(r, c) ((unsigned)((r) * 128 + ((((c) ^ ((r) & 7))) << 4)))

#define ISSUE_STAGE(sidx, k0)                                                  \
    do {                                                                       \
        const unsigned tb = sb + (unsigned)(sidx) * STAGEB;                    \
        _Pragma("unroll")                                                      \
        for (int it = 0; it < 4; it++) {                                       \
            const int r = r0c + it * 32;                                       \
            const unsigned so = SWOFF(r, c0c);                                 \
            const size_t ao = (size_t)(bm + r) * K + (k0) + c0c * 8;           \
            const int brw = bn + r;                                            \
            const int pz  = (brw < N) ? 16 : 0;                                \
            const size_t bo = (size_t)((brw < N) ? brw : 0) * K + (k0) + c0c * 8; \
            cpa16 (tb + so,         A + ao);                                   \
            cpa16p(tb + TILEB + so, B + bo, pz);                               \
        }                                                                      \
        asm volatile("cp.async.commit_group;");                                \
    } while (0)

    float acc[2][8][4];
#pragma unroll
    for (int mi = 0; mi < 2; mi++)
#pragma unroll
        for (int ni = 0; ni < 8; ni++)
#pragma unroll
            for (int r = 0; r < 4; r++) acc[mi][ni][r] = 0.f;

    ISSUE_STAGE(0, 0);
    ISSUE_STAGE(1, 64);

    const int a_row = ((lane >> 3) & 1) * 8 + (lane & 7);
    const int a_ch  = (lane >> 4) & 1;
    const int b_row = ((lane >> 4) & 1) * 8 + (lane & 7);
    const int b_ch  = (lane >> 3) & 1;

    for (int kt = 0; kt < KT; kt++) {
        asm volatile("cp.async.wait_group %0;" :: "n"(1));
        __syncthreads();

        if (kt + 2 < KT) ISSUE_STAGE((kt + 2) % NSTG, (kt + 2) * 64);
        else             asm volatile("cp.async.commit_group;");

        const unsigned stb = sb + (unsigned)(kt % NSTG) * STAGEB;

#pragma unroll
        for (int ks = 0; ks < 4; ks++) {
            unsigned fA[2][4], fB[8][2];
            const int ca = ks * 2 + a_ch;
            const int cb = ks * 2 + b_ch;

#pragma unroll
            for (int mi = 0; mi < 2; mi++) {
                const int r = wm + mi * 16 + a_row;
                const unsigned ad = stb + SWOFF(r, ca);
                asm volatile("ldmatrix.sync.aligned.m8n8.x4.shared.b16 {%0,%1,%2,%3}, [%4];"
                    : "=r"(fA[mi][0]), "=r"(fA[mi][1]), "=r"(fA[mi][2]), "=r"(fA[mi][3])
                    : "r"(ad));
            }
#pragma unroll
            for (int p = 0; p < 4; p++) {
                const int r = wn + p * 16 + b_row;
                const unsigned bd = stb + TILEB + SWOFF(r, cb);
                asm volatile("ldmatrix.sync.aligned.m8n8.x4.shared.b16 {%0,%1,%2,%3}, [%4];"
                    : "=r"(fB[2*p][0]), "=r"(fB[2*p][1]), "=r"(fB[2*p+1][0]), "=r"(fB[2*p+1][1])
                    : "r"(bd));
            }

#define MMA(d, a, b)                                                           \
    asm volatile("mma.sync.aligned.m16n8k16.row.col.f32.f16.f16.f32 "          \
                 "{%0,%1,%2,%3}, {%4,%5,%6,%7}, {%8,%9}, {%0,%1,%2,%3};"       \
                 : "+f"((d)[0]), "+f"((d)[1]), "+f"((d)[2]), "+f"((d)[3])      \
                 : "r"((a)[0]), "r"((a)[1]), "r"((a)[2]), "r"((a)[3]),         \
                   "r"((b)[0]), "r"((b)[1]))

#pragma unroll
            for (int ni = 0; ni < 8; ni++)
#pragma unroll
                for (int mi = 0; mi < 2; mi++)
                    MMA(acc[mi][ni], fA[mi], fB[ni]);
#undef MMA
        }
    }

    // epilogue
#pragma unroll
    for (int mi = 0; mi < 2; mi++) {
        const int row = bm + wm + mi * 16 + g;
#pragma unroll
        for (int ni = 0; ni < 8; ni++) {
            const int col = bn + wn + ni * 8 + tg * 2;
            if (col < N) {
                const float bx = bias[col], by = bias[col + 1];
                float2 v0 = make_float2(acc[mi][ni][0] + bx, acc[mi][ni][1] + by);
                float2 v1 = make_float2(acc[mi][ni][2] + bx, acc[mi][ni][3] + by);
                *(float2*)(C + (size_t)row * N + col)       = v0;
                *(float2*)(C + (size_t)(row + 8) * N + col) = v1;
            }
        }
    }
#undef ISSUE_STAGE
#undef SWOFF
}

// ---------------------------------------------------------------------------
// Fused RoPE: q heads (cols 0..4095) + k heads (cols 4096..4607), in-place.
// ---------------------------------------------------------------------------
__global__ void rope_all(float* __restrict__ t, const float* __restrict__ rope)
{
    const int idx = blockIdx.x * blockDim.x + threadIdx.x;
    const int total = SEQ * (NH + NKV) * 32;
    if (idx >= total) return;
    const int d  = idx & 31;
    const int hh = (idx >> 5) % (NH + NKV);
    const int s  = idx / (32 * (NH + NKV));
    const int coff = (hh < NH) ? hh * HD : KOFF + (hh - NH) * HD;

    const float c1 = rope[s * 128 + d];
    const float c2 = rope[s * 128 + d + 32];
    const float s1 = rope[s * 128 + 64 + d];
    const float s2 = rope[s * 128 + 96 + d];

    float* base = t + (size_t)s * QKVN + coff;
    const float x1 = base[d];
    const float x2 = base[d + 32];
    base[d]      = x1 * c1 - x2 * s1;
    base[d + 32] = x2 * c2 + x1 * s2;
}

// ---------------------------------------------------------------------------
// smem-staged sliding-window attention + sink gating.
// CTA = (head, block of 32 queries). K/V window (<=160 rows) staged in smem
// with float4 rotation swizzle (chunk (c4+row)&15) -> conflict-free reads.
// 8 warps x 4 queries. Writes fp16 output for the O-proj GEMM.
// ---------------------------------------------------------------------------
#define JMAX 160
#define ASMEM_FLOATS (2*JMAX*64 + 8*64 + 8*128)   // sK, sV, shq, shp
#define ASMEM_BYTES  (ASMEM_FLOATS*4)             // 88064

__global__ __launch_bounds__(256, 2) void attn_kernel(
    const float* __restrict__ qkv, const float* __restrict__ sinks,
    f16* __restrict__ o16)
{
    extern __shared__ float asm_[];
    float* sK  = asm_;
    float* sV  = asm_ + JMAX * 64;
    float* shq = asm_ + 2 * JMAX * 64;     // [8][64]
    float* shp = shq + 8 * 64;             // [8][128]

    const float scale = 0.16832169945461f;  // (0.1*ln(32)+1)/8
    const int tid  = threadIdx.x;
    const int w    = tid >> 5;
    const int lane = tid & 31;
    const int h    = blockIdx.x >> 6;      // 64 query-blocks per head
    const int ib   = blockIdx.x & 63;
    const int i0   = ib * 32;
    const int kvh  = h >> 3;

    int jmin = i0 - (WINDOW - 1); if (jmin < 0) jmin = 0;
    const int jcnt = i0 + 31 - jmin + 1;   // <= 159

    // stage K and V windows (rotated float4 chunks)
    for (int idx = tid; idx < jcnt * 16; idx += 256) {
        const int row = idx >> 4, c4 = idx & 15;
        const int rc  = (c4 + row) & 15;
        const size_t rb = (size_t)(jmin + row) * QKVN + kvh * HD;
        *(float4*)(sK + row * 64 + rc * 4) =
            *(const float4*)(qkv + rb + KOFF + c4 * 4);
        *(float4*)(sV + row * 64 + rc * 4) =
            *(const float4*)(qkv + rb + VOFF + c4 * 4);
    }
    __syncthreads();

    const float snk = sinks[h];

#pragma unroll
    for (int qi = 0; qi < 4; qi++) {
        const int i = i0 + w * 4 + qi;

        const float* qrow = qkv + (size_t)i * QKVN + h * HD;
        shq[w * 64 + lane]      = qrow[lane];
        shq[w * 64 + lane + 32] = qrow[lane + 32];
        __syncwarp();

        int start = i - (WINDOW - 1); if (start < jmin) start = jmin;
        const int cnt   = i - start + 1;
        const int sbase = start - jmin;

        float sc[4];
#pragma unroll
        for (int t = 0; t < 4; t++) {
            const int jj = lane + 32 * t;
            if (jj < cnt) {
                const int r = sbase + jj;
                float s = 0.f;
#pragma unroll
                for (int d4 = 0; d4 < 16; d4++) {
                    const int rc = (d4 + r) & 15;
                    const float4 kk = *(const float4*)(sK + r * 64 + rc * 4);
                    s = fmaf(kk.x, shq[w * 64 + d4 * 4 + 0], s);
                    s = fmaf(kk.y, shq[w * 64 + d4 * 4 + 1], s);
                    s = fmaf(kk.z, shq[w * 64 + d4 * 4 + 2], s);
                    s = fmaf(kk.w, shq[w * 64 + d4 * 4 + 3], s);
                }
                sc[t] = s * scale;
            } else {
                sc[t] = -1e30f;
            }
        }

        float m = fmaxf(fmaxf(sc[0], sc[1]), fmaxf(sc[2], sc[3]));
#pragma unroll
        for (int o = 16; o; o >>= 1) m = fmaxf(m, __shfl_xor_sync(0xffffffffu, m, o));

        float e[4], sum = 0.f;
#pragma unroll
        for (int t = 0; t < 4; t++) { e[t] = expf(sc[t] - m); sum += e[t]; }
#pragma unroll
        for (int o = 16; o; o >>= 1) sum += __shfl_xor_sync(0xffffffffu, sum, o);

        const float lse = m + logf(sum);
        const float sig = 1.f / (1.f + expf(snk - lse));
        const float wsc = sig / sum;
#pragma unroll
        for (int t = 0; t < 4; t++) shp[w * 128 + lane + 32 * t] = e[t] * wsc;
        __syncwarp();

        // V accumulate: lane owns dims {lane, lane+32}; dual accumulators
        const int c0 = lane >> 2, q0 = lane & 3;
        const int c1 = (lane + 32) >> 2;
        float e0 = 0.f, e1 = 0.f, o0 = 0.f, o1 = 0.f;
        int jj = 0;
        for (; jj + 1 < cnt; jj += 2) {
            const float pa = shp[w * 128 + jj];
            const float pb = shp[w * 128 + jj + 1];
            const int ra = sbase + jj, rb2 = ra + 1;
            e0 = fmaf(pa, sV[ra * 64 + (((c0 + ra) & 15) << 2) + q0], e0);
            e1 = fmaf(pa, sV[ra * 64 + (((c1 + ra) & 15) << 2) + q0], e1);
            o0 = fmaf(pb, sV[rb2 * 64 + (((c0 + rb2) & 15) << 2) + q0], o0);
            o1 = fmaf(pb, sV[rb2 * 64 + (((c1 + rb2) & 15) << 2) + q0], o1);
        }
        if (jj < cnt) {
            const float pa = shp[w * 128 + jj];
            const int ra = sbase + jj;
            e0 = fmaf(pa, sV[ra * 64 + (((c0 + ra) & 15) << 2) + q0], e0);
            e1 = fmaf(pa, sV[ra * 64 + (((c1 + ra) & 15) << 2) + q0], e1);
        }

        const size_t ob = (size_t)i * QDIM + h * HD;
        o16[ob + lane]      = __float2half_rn(e0 + o0);
        o16[ob + lane + 32] = __float2half_rn(e1 + o1);
    }
}

// ---------------------------------------------------------------------------
extern "C" void kernel_launch(void* const* d_in, const int* in_sizes, int n_in,
                              void* d_out, int out_size)
{
    const float* x     = (const float*)d_in[0];
    const float* rope  = (const float*)d_in[1];
    const float* wq_w  = (const float*)d_in[2];
    const float* wq_b  = (const float*)d_in[3];
    const float* wk_w  = (const float*)d_in[4];
    const float* wk_b  = (const float*)d_in[5];
    const float* wv_w  = (const float*)d_in[6];
    const float* wv_b  = (const float*)d_in[7];
    const float* wo_w  = (const float*)d_in[8];
    const float* wo_b  = (const float*)d_in[9];
    const float* sinks = (const float*)d_in[10];
    float* out = (float*)d_out;

    float *qkv, *bqkv;
    cudaGetSymbolAddress((void**)&qkv,  g_qkv);
    cudaGetSymbolAddress((void**)&bqkv, g_bqkv);

    f16 *x16, *wc, *wo, *a16;
    cudaGetSymbolAddress((void**)&x16, g_x16);
    cudaGetSymbolAddress((void**)&wc, g_wc); cudaGetSymbolAddress((void**)&wo, g_wo);
    cudaGetSymbolAddress((void**)&a16, g_a16);

    cudaFuncSetAttribute(gemm_f16, cudaFuncAttributeMaxDynamicSharedMemorySize,
                         GSMEM_BYTES);
    cudaFuncSetAttribute(attn_kernel, cudaFuncAttributeMaxDynamicSharedMemorySize,
                         ASMEM_BYTES);

    // fused prep
    prep<<<(unsigned)((PREP_THREADS + 255) / 256), 256>>>(
        x, wq_w, wk_w, wv_w, wo_w, wq_b, wk_b, wv_b,
        x16, wc, wo, bqkv);

    // fused QKV projection: [2048 x 5120]
    gemm_f16<<<dim3(QKVN / 128, SEQ / 128), 256, GSMEM_BYTES>>>(
        x16, wc, bqkv, qkv, SEQ, QKVN, DIM);

    // fused RoPE (q + k)
    rope_all<<<(SEQ * (NH + NKV) * 32 + 255) / 256, 256>>>(qkv, rope);

    // smem-staged attention
    attn_kernel<<<NH * (SEQ / 32), 256, ASMEM_BYTES>>>(qkv, sinks, a16);

    // O-projection
    gemm_f16<<<dim3((DIM + 127) / 128, SEQ / 128), 256, GSMEM_BYTES>>>(
        a16, wo, wo_b, out, SEQ, DIM, QDIM);
}

// round 12
// speedup vs baseline: 4.4231x; 1.4399x over previous
#include <cuda_runtime.h>
#include <cuda_fp16.h>
#include <math.h>

#define SEQ 2048
#define DIM 2880
#define NH 64
#define NKV 8
#define HD 64
#define QDIM (NH*HD)     // 4096
#define KVDIM (NKV*HD)   // 512
#define QKVN 5120        // 4096 + 512 + 512
#define KOFF 4096
#define VOFF 4608
#define WINDOW 128

typedef __half f16;

// fp32 scratch
__device__ float g_qkv[SEQ * QKVN];    // 40 MB: q | k | v per row
__device__ float g_bqkv[QKVN];

// fp16 operand scratch
__device__ f16 g_x16[SEQ * DIM];       // x (fp16)
__device__ f16 g_wc[QKVN * DIM];       // concat wq|wk|wv (fp16)
__device__ f16 g_wo[DIM * QDIM];       // wo (fp16)
__device__ f16 g_a16[SEQ * QDIM];      // attn out (fp16)

// ---------------------------------------------------------------------------
// Fused prep: x -> fp16, wq/wk/wv -> wc fp16, wo -> fp16, bias concat.
// ---------------------------------------------------------------------------
#define R0 (SEQ*DIM/8)
#define R1 (QDIM*DIM/8)
#define R2 (KVDIM*DIM/8)
#define R3 (KVDIM*DIM/8)
#define R4 ((size_t)DIM*QDIM/8)
#define R5 (QKVN/8)
#define PREP_THREADS (R0+R1+R2+R3+R4+R5)

__device__ __forceinline__ void conv8(const float* __restrict__ s, f16* __restrict__ d) {
    float4 a = *(const float4*)s;
    float4 b = *(const float4*)(s + 4);
    __half2 hh[4];
    hh[0] = __halves2half2(__float2half_rn(a.x), __float2half_rn(a.y));
    hh[1] = __halves2half2(__float2half_rn(a.z), __float2half_rn(a.w));
    hh[2] = __halves2half2(__float2half_rn(b.x), __float2half_rn(b.y));
    hh[3] = __halves2half2(__float2half_rn(b.z), __float2half_rn(b.w));
    *(uint4*)d = *(uint4*)hh;
}

__global__ void prep(const float* __restrict__ x,
                     const float* __restrict__ wq, const float* __restrict__ wk,
                     const float* __restrict__ wv, const float* __restrict__ wo,
                     const float* __restrict__ qb, const float* __restrict__ kb,
                     const float* __restrict__ vb,
                     f16* __restrict__ x16,
                     f16* __restrict__ wc, f16* __restrict__ wo16,
                     float* __restrict__ bqkv)
{
    long t = (long)blockIdx.x * blockDim.x + threadIdx.x;
    if (t < (long)R0) { conv8(x + t * 8, x16 + t * 8); return; }
    t -= R0;
    if (t < (long)R1) { conv8(wq + t * 8, wc + t * 8); return; }
    t -= R1;
    if (t < (long)R2) { conv8(wk + t * 8, wc + (size_t)KOFF * DIM + t * 8); return; }
    t -= R2;
    if (t < (long)R3) { conv8(wv + t * 8, wc + (size_t)VOFF * DIM + t * 8); return; }
    t -= R3;
    if (t < (long)R4) { conv8(wo + t * 8, wo16 + t * 8); return; }
    t -= R4;
    if (t < (long)R5) {
        const int i = (int)t * 8;
#pragma unroll
        for (int j = 0; j < 8; j++) {
            const int c = i + j;
            bqkv[c] = (c < KOFF) ? qb[c] : (c < VOFF ? kb[c - KOFF] : vb[c - VOFF]);
        }
    }
}

// ---------------------------------------------------------------------------
// fp16 mma.sync GEMM (NT): C = A*B^T + bias
// Block 128x128, BK=64, 3-stage cp.async ring, SW128-swizzled 128B rows,
// 256 thr = 8 warps (4m x 2n), warp tile 32x64. 2 CTAs/SM (192KB smem).
// ---------------------------------------------------------------------------
#define TILEB 16384u                // one operand tile: 128 rows x 128 bytes
#define STAGEB (2u*TILEB)           // A, B = 32 KB
#define NSTG 3
#define GSMEM_BYTES (NSTG*STAGEB)   // 96 KB

__device__ __forceinline__ void cpa16(unsigned dst, const void* src) {
    asm volatile("cp.async.cg.shared.global [%0], [%1], 16;" :: "r"(dst), "l"(src));
}
__device__ __forceinline__ void cpa16p(unsigned dst, const void* src, int sz) {
    asm volatile("cp.async.cg.shared.global [%0], [%1], 16, %2;"
                 :: "r"(dst), "l"(src), "r"(sz));
}

__global__ __launch_bounds__(256, 2) void gemm_f16(
    const f16* __restrict__ A, const f16* __restrict__ B,
    const float* __restrict__ bias, float* __restrict__ C,
    int M, int N, int K)
{
    extern __shared__ char dsm[];
    unsigned sb;
    { unsigned long long t = __cvta_generic_to_shared(dsm); sb = (unsigned)t; }

    const int tid  = threadIdx.x;
    const int wid  = tid >> 5;
    const int lane = tid & 31;
    const int bm   = blockIdx.y * 128;
    const int bn   = blockIdx.x * 128;
    const int wm   = (wid & 3) * 32;
    const int wn   = (wid >> 2) * 64;
    const int g    = lane >> 2;
    const int tg   = lane & 3;

    const int KT = K / 64;

    const int r0c = tid >> 3;            // base row 0..31 (stride 32)
    const int c0c = tid & 7;             // 16B segment 0..7

#define SWOFF(r, c) ((unsigned)((r) * 128 + ((((c) ^ ((r) & 7))) << 4)))

#define ISSUE_STAGE(sidx, k0)                                                  \
    do {                                                                       \
        const unsigned tb = sb + (unsigned)(sidx) * STAGEB;                    \
        _Pragma("unroll")                                                      \
        for (int it = 0; it < 4; it++) {                                       \
            const int r = r0c + it * 32;                                       \
            const unsigned so = SWOFF(r, c0c);                                 \
            const size_t ao = (size_t)(bm + r) * K + (k0) + c0c * 8;           \
            const int brw = bn + r;                                            \
            const int pz  = (brw < N) ? 16 : 0;                                \
            const size_t bo = (size_t)((brw < N) ? brw : 0) * K + (k0) + c0c * 8; \
            cpa16 (tb + so,         A + ao);                                   \
            cpa16p(tb + TILEB + so, B + bo, pz);                               \
        }                                                                      \
        asm volatile("cp.async.commit_group;");                                \
    } while (0)

    float acc[2][8][4];
#pragma unroll
    for (int mi = 0; mi < 2; mi++)
#pragma unroll
        for (int ni = 0; ni < 8; ni++)
#pragma unroll
            for (int r = 0; r < 4; r++) acc[mi][ni][r] = 0.f;

    ISSUE_STAGE(0, 0);
    ISSUE_STAGE(1, 64);

    const int a_row = ((lane >> 3) & 1) * 8 + (lane & 7);
    const int a_ch  = (lane >> 4) & 1;
    const int b_row = ((lane >> 4) & 1) * 8 + (lane & 7);
    const int b_ch  = (lane >> 3) & 1;

    for (int kt = 0; kt < KT; kt++) {
        asm volatile("cp.async.wait_group %0;" :: "n"(1));
        __syncthreads();

        if (kt + 2 < KT) ISSUE_STAGE((kt + 2) % NSTG, (kt + 2) * 64);
        else             asm volatile("cp.async.commit_group;");

        const unsigned stb = sb + (unsigned)(kt % NSTG) * STAGEB;

#pragma unroll
        for (int ks = 0; ks < 4; ks++) {
            unsigned fA[2][4], fB[8][2];
            const int ca = ks * 2 + a_ch;
            const int cb = ks * 2 + b_ch;

#pragma unroll
            for (int mi = 0; mi < 2; mi++) {
                const int r = wm + mi * 16 + a_row;
                const unsigned ad = stb + SWOFF(r, ca);
                asm volatile("ldmatrix.sync.aligned.m8n8.x4.shared.b16 {%0,%1,%2,%3}, [%4];"
                    : "=r"(fA[mi][0]), "=r"(fA[mi][1]), "=r"(fA[mi][2]), "=r"(fA[mi][3])
                    : "r"(ad));
            }
#pragma unroll
            for (int p = 0; p < 4; p++) {
                const int r = wn + p * 16 + b_row;
                const unsigned bd = stb + TILEB + SWOFF(r, cb);
                asm volatile("ldmatrix.sync.aligned.m8n8.x4.shared.b16 {%0,%1,%2,%3}, [%4];"
                    : "=r"(fB[2*p][0]), "=r"(fB[2*p][1]), "=r"(fB[2*p+1][0]), "=r"(fB[2*p+1][1])
                    : "r"(bd));
            }

#define MMA(d, a, b)                                                           \
    asm volatile("mma.sync.aligned.m16n8k16.row.col.f32.f16.f16.f32 "          \
                 "{%0,%1,%2,%3}, {%4,%5,%6,%7}, {%8,%9}, {%0,%1,%2,%3};"       \
                 : "+f"((d)[0]), "+f"((d)[1]), "+f"((d)[2]), "+f"((d)[3])      \
                 : "r"((a)[0]), "r"((a)[1]), "r"((a)[2]), "r"((a)[3]),         \
                   "r"((b)[0]), "r"((b)[1]))

#pragma unroll
            for (int ni = 0; ni < 8; ni++)
#pragma unroll
                for (int mi = 0; mi < 2; mi++)
                    MMA(acc[mi][ni], fA[mi], fB[ni]);
#undef MMA
        }
    }

    // epilogue
#pragma unroll
    for (int mi = 0; mi < 2; mi++) {
        const int row = bm + wm + mi * 16 + g;
#pragma unroll
        for (int ni = 0; ni < 8; ni++) {
            const int col = bn + wn + ni * 8 + tg * 2;
            if (col < N) {
                const float bx = bias[col], by = bias[col + 1];
                float2 v0 = make_float2(acc[mi][ni][0] + bx, acc[mi][ni][1] + by);
                float2 v1 = make_float2(acc[mi][ni][2] + bx, acc[mi][ni][3] + by);
                *(float2*)(C + (size_t)row * N + col)       = v0;
                *(float2*)(C + (size_t)(row + 8) * N + col) = v1;
            }
        }
    }
#undef ISSUE_STAGE
#undef SWOFF
}

// ---------------------------------------------------------------------------
// Fused RoPE: q heads (cols 0..4095) + k heads (cols 4096..4607), in-place.
// ---------------------------------------------------------------------------
__global__ void rope_all(float* __restrict__ t, const float* __restrict__ rope)
{
    const int idx = blockIdx.x * blockDim.x + threadIdx.x;
    const int total = SEQ * (NH + NKV) * 32;
    if (idx >= total) return;
    const int d  = idx & 31;
    const int hh = (idx >> 5) % (NH + NKV);
    const int s  = idx / (32 * (NH + NKV));
    const int coff = (hh < NH) ? hh * HD : KOFF + (hh - NH) * HD;

    const float c1 = rope[s * 128 + d];
    const float c2 = rope[s * 128 + d + 32];
    const float s1 = rope[s * 128 + 64 + d];
    const float s2 = rope[s * 128 + 96 + d];

    float* base = t + (size_t)s * QKVN + coff;
    const float x1 = base[d];
    const float x2 = base[d + 32];
    base[d]      = x1 * c1 - x2 * s1;
    base[d + 32] = x2 * c2 + x1 * s2;
}

// ---------------------------------------------------------------------------
// smem-staged sliding-window attention + sink gating, query-inner blocked.
// CTA = (head, 32 queries). Warp = 4 queries, processed TOGETHER:
// each K/V smem read is shared by 4 queries (4x less LDS traffic than R10).
// K rotated-chunk layout; V plain stride-64 (lane<->dim, conflict-free).
// ---------------------------------------------------------------------------
#define JMAX 160
#define ASMEM_FLOATS (2*JMAX*64 + 8*4*64 + 8*JMAX*4)  // sK, sV, shq, shp
#define ASMEM_BYTES  (ASMEM_FLOATS*4)                 // 110592

__global__ __launch_bounds__(256, 2) void attn_kernel(
    const float* __restrict__ qkv, const float* __restrict__ sinks,
    f16* __restrict__ o16)
{
    extern __shared__ float asm_[];
    float* sK  = asm_;                    // [160][64], rotated 16B chunks
    float* sV  = asm_ + JMAX * 64;        // [160][64], plain
    float* shq = asm_ + 2 * JMAX * 64;    // [8][4][64]
    float* shp = shq + 8 * 4 * 64;        // [8][160][4]

    const float scale = 0.16832169945461f;  // (0.1*ln(32)+1)/8
    const int tid  = threadIdx.x;
    const int w    = tid >> 5;
    const int lane = tid & 31;
    const int h    = blockIdx.x >> 6;
    const int ib   = blockIdx.x & 63;
    const int i0   = ib * 32;
    const int kvh  = h >> 3;

    int jmin = i0 - (WINDOW - 1); if (jmin < 0) jmin = 0;
    const int jcnt = i0 + 31 - jmin + 1;   // <= 159

    // stage K (rotated) and V (plain)
    for (int idx = tid; idx < jcnt * 16; idx += 256) {
        const int row = idx >> 4, c4 = idx & 15;
        const size_t rb = (size_t)(jmin + row) * QKVN + kvh * HD;
        *(float4*)(sK + row * 64 + (((c4 + row) & 15) << 2)) =
            *(const float4*)(qkv + rb + KOFF + c4 * 4);
        *(float4*)(sV + row * 64 + (c4 << 2)) =
            *(const float4*)(qkv + rb + VOFF + c4 * 4);
    }

    // stage this warp's 4 queries
    const int iw = i0 + w * 4;
    float* q_ = shq + w * 256;
#pragma unroll
    for (int qi = 0; qi < 4; qi++) {
        const float* qrow = qkv + (size_t)(iw + qi) * QKVN + h * HD;
        q_[qi * 64 + lane]      = qrow[lane];
        q_[qi * 64 + lane + 32] = qrow[lane + 32];
    }
    __syncthreads();

    int wlo = iw - (WINDOW - 1); if (wlo < 0) wlo = 0;
    const int cntw = iw + 3 - wlo + 1;     // <= 131
    const int roff = wlo - jmin;           // >= 0

    // per-lane-group staged rows (clamped; invalid lanes masked later)
    int rr[5]; bool inb[5];
#pragma unroll
    for (int t = 0; t < 5; t++) {
        const int jj = lane + 32 * t;
        inb[t] = (jj < cntw);
        int r = roff + jj;
        if (r > JMAX - 1) r = JMAX - 1;
        rr[t] = r;
    }

    // scores: read each K float4 once, FMA into 4 queries
    float dot[5][4];
#pragma unroll
    for (int t = 0; t < 5; t++)
#pragma unroll
        for (int qi = 0; qi < 4; qi++) dot[t][qi] = 0.f;

#pragma unroll
    for (int d4 = 0; d4 < 16; d4++) {
        float4 qv[4];
#pragma unroll
        for (int qi = 0; qi < 4; qi++)
            qv[qi] = *(const float4*)(q_ + qi * 64 + d4 * 4);
#pragma unroll
        for (int t = 0; t < 5; t++) {
            const int r = rr[t];
            const float4 kk = *(const float4*)(sK + r * 64 + (((d4 + r) & 15) << 2));
#pragma unroll
            for (int qi = 0; qi < 4; qi++) {
                dot[t][qi] = fmaf(kk.x, qv[qi].x, dot[t][qi]);
                dot[t][qi] = fmaf(kk.y, qv[qi].y, dot[t][qi]);
                dot[t][qi] = fmaf(kk.z, qv[qi].z, dot[t][qi]);
                dot[t][qi] = fmaf(kk.w, qv[qi].w, dot[t][qi]);
            }
        }
    }

    // per-query masked softmax + sink gating; p written back into dot[][]
    const float snk = sinks[h];
#pragma unroll
    for (int qi = 0; qi < 4; qi++) {
        const int i = iw + qi;
        float s[5];
#pragma unroll
        for (int t = 0; t < 5; t++) {
            const int j = wlo + lane + 32 * t;
            const bool v = inb[t] && (j <= i) && (j >= i - (WINDOW - 1));
            s[t] = v ? dot[t][qi] * scale : -1e30f;
        }
        float m = fmaxf(fmaxf(fmaxf(s[0], s[1]), fmaxf(s[2], s[3])), s[4]);
#pragma unroll
        for (int o = 16; o; o >>= 1) m = fmaxf(m, __shfl_xor_sync(0xffffffffu, m, o));
        float sum = 0.f;
#pragma unroll
        for (int t = 0; t < 5; t++) { s[t] = expf(s[t] - m); sum += s[t]; }
#pragma unroll
        for (int o = 16; o; o >>= 1) sum += __shfl_xor_sync(0xffffffffu, sum, o);
        const float lse = m + logf(sum);
        const float wsc = (1.f / (1.f + expf(snk - lse))) / sum;
#pragma unroll
        for (int t = 0; t < 5; t++) dot[t][qi] = s[t] * wsc;
    }

    // pack p: shp[w][jrel][qi] (float4 per row; invalid rows are exact zeros)
    float* p_ = shp + w * (JMAX * 4);
#pragma unroll
    for (int t = 0; t < 5; t++) {
        const int jj = lane + 32 * t;     // <= 159
        *(float4*)(p_ + jj * 4) =
            make_float4(dot[t][0], dot[t][1], dot[t][2], dot[t][3]);
    }
    __syncwarp();

    // V accumulate: read each V row pair once, FMA into 4 queries
    float a[4][2];
#pragma unroll
    for (int qi = 0; qi < 4; qi++) { a[qi][0] = 0.f; a[qi][1] = 0.f; }

    const float* vb0 = sV + roff * 64;
    for (int jrel = 0; jrel < cntw; jrel++) {
        const float4 p4 = *(const float4*)(p_ + jrel * 4);
        const float v0 = vb0[jrel * 64 + lane];
        const float v1 = vb0[jrel * 64 + lane + 32];
        a[0][0] = fmaf(p4.x, v0, a[0][0]); a[0][1] = fmaf(p4.x, v1, a[0][1]);
        a[1][0] = fmaf(p4.y, v0, a[1][0]); a[1][1] = fmaf(p4.y, v1, a[1][1]);
        a[2][0] = fmaf(p4.z, v0, a[2][0]); a[2][1] = fmaf(p4.z, v1, a[2][1]);
        a[3][0] = fmaf(p4.w, v0, a[3][0]); a[3][1] = fmaf(p4.w, v1, a[3][1]);
    }

#pragma unroll
    for (int qi = 0; qi < 4; qi++) {
        const size_t ob = (size_t)(iw + qi) * QDIM + h * HD;
        o16[ob + lane]      = __float2half_rn(a[qi][0]);
        o16[ob + lane + 32] = __float2half_rn(a[qi][1]);
    }
}

// ---------------------------------------------------------------------------
extern "C" void kernel_launch(void* const* d_in, const int* in_sizes, int n_in,
                              void* d_out, int out_size)
{
    const float* x     = (const float*)d_in[0];
    const float* rope  = (const float*)d_in[1];
    const float* wq_w  = (const float*)d_in[2];
    const float* wq_b  = (const float*)d_in[3];
    const float* wk_w  = (const float*)d_in[4];
    const float* wk_b  = (const float*)d_in[5];
    const float* wv_w  = (const float*)d_in[6];
    const float* wv_b  = (const float*)d_in[7];
    const float* wo_w  = (const float*)d_in[8];
    const float* wo_b  = (const float*)d_in[9];
    const float* sinks = (const float*)d_in[10];
    float* out = (float*)d_out;

    float *qkv, *bqkv;
    cudaGetSymbolAddress((void**)&qkv,  g_qkv);
    cudaGetSymbolAddress((void**)&bqkv, g_bqkv);

    f16 *x16, *wc, *wo, *a16;
    cudaGetSymbolAddress((void**)&x16, g_x16);
    cudaGetSymbolAddress((void**)&wc, g_wc); cudaGetSymbolAddress((void**)&wo, g_wo);
    cudaGetSymbolAddress((void**)&a16, g_a16);

    cudaFuncSetAttribute(gemm_f16, cudaFuncAttributeMaxDynamicSharedMemorySize,
                         GSMEM_BYTES);
    cudaFuncSetAttribute(attn_kernel, cudaFuncAttributeMaxDynamicSharedMemorySize,
                         ASMEM_BYTES);

    // fused prep
    prep<<<(unsigned)((PREP_THREADS + 255) / 256), 256>>>(
        x, wq_w, wk_w, wv_w, wo_w, wq_b, wk_b, wv_b,
        x16, wc, wo, bqkv);

    // fused QKV projection: [2048 x 5120]
    gemm_f16<<<dim3(QKVN / 128, SEQ / 128), 256, GSMEM_BYTES>>>(
        x16, wc, bqkv, qkv, SEQ, QKVN, DIM);

    // fused RoPE (q + k)
    rope_all<<<(SEQ * (NH + NKV) * 32 + 255) / 256, 256>>>(qkv, rope);

    // query-inner blocked attention
    attn_kernel<<<NH * (SEQ / 32), 256, ASMEM_BYTES>>>(qkv, sinks, a16);

    // O-projection
    gemm_f16<<<dim3((DIM + 127) / 128, SEQ / 128), 256, GSMEM_BYTES>>>(
        a16, wo, wo_b, out, SEQ, DIM, QDIM);
}